// round 1
// baseline (speedup 1.0000x reference)
#include <cuda_runtime.h>
#include <cuda_bf16.h>
#include <math.h>

// Problem constants
#define BATCH 4
#define SEQ   2048
#define DMODEL 1024
#define NHEADS 16
#define DK    64
#define MROWS (BATCH * SEQ)   // 8192

// ---------------- scratch (static device globals; no runtime allocation) ----
__device__ float g_q[MROWS * DMODEL];
__device__ float g_k[MROWS * DMODEL];
__device__ float g_v[MROWS * DMODEL];
__device__ float g_attn[MROWS * DMODEL];

// ---------------- GEMM: C[M,N] = A[M,K] @ B[N,K]^T + bias[N] -----------------
// Tiles: BM=128, BN=64, BK=16. 256 threads, each computes 8x4.
__global__ __launch_bounds__(256) void gemm_nt_kernel(
    const float* __restrict__ A, const float* __restrict__ Bw,
    const float* __restrict__ bias, float* __restrict__ C,
    int M, int N, int K)
{
    __shared__ float As[16][130];  // [k][m], padded: conflict-free stores/loads
    __shared__ float Bs[16][66];   // [k][n]

    const int tid = threadIdx.x;
    const int tx = tid & 15;       // 0..15 -> 4 cols each
    const int ty = tid >> 4;       // 0..15 -> 8 rows each
    const int m0 = blockIdx.y * 128;
    const int n0 = blockIdx.x * 64;

    float acc[8][4];
#pragma unroll
    for (int i = 0; i < 8; i++)
#pragma unroll
        for (int j = 0; j < 4; j++) acc[i][j] = 0.f;

    const int lrB = tid >> 2;        // 0..63
    const int lkB = (tid & 3) * 4;   // 0,4,8,12

    for (int k0 = 0; k0 < K; k0 += 16) {
        // Stage A tile (128x16): 2 float4 per thread
#pragma unroll
        for (int n = 0; n < 2; n++) {
            int c = tid + n * 256;
            int r = c >> 2;
            int kk = (c & 3) * 4;
            float4 v = *(const float4*)(A + (size_t)(m0 + r) * K + k0 + kk);
            As[kk + 0][r] = v.x; As[kk + 1][r] = v.y;
            As[kk + 2][r] = v.z; As[kk + 3][r] = v.w;
        }
        // Stage B tile (64x16): 1 float4 per thread
        {
            float4 v = *(const float4*)(Bw + (size_t)(n0 + lrB) * K + k0 + lkB);
            Bs[lkB + 0][lrB] = v.x; Bs[lkB + 1][lrB] = v.y;
            Bs[lkB + 2][lrB] = v.z; Bs[lkB + 3][lrB] = v.w;
        }
        __syncthreads();

#pragma unroll
        for (int kk = 0; kk < 16; kk++) {
            float a[8], bb[4];
#pragma unroll
            for (int i = 0; i < 8; i++) a[i] = As[kk][ty * 8 + i];
#pragma unroll
            for (int j = 0; j < 4; j++) bb[j] = Bs[kk][tx * 4 + j];
#pragma unroll
            for (int i = 0; i < 8; i++)
#pragma unroll
                for (int j = 0; j < 4; j++) acc[i][j] += a[i] * bb[j];
        }
        __syncthreads();
    }

    float4 bv = *(const float4*)(bias + n0 + tx * 4);
#pragma unroll
    for (int i = 0; i < 8; i++) {
        float4 o;
        o.x = acc[i][0] + bv.x;
        o.y = acc[i][1] + bv.y;
        o.z = acc[i][2] + bv.z;
        o.w = acc[i][3] + bv.w;
        *(float4*)(C + (size_t)(m0 + ty * 8 + i) * N + n0 + tx * 4) = o;
    }
}

// ---------------- Flash attention (fp32, online softmax) --------------------
// Block: (b, h, q-tile of 64 rows). 256 threads = 16x16, 4x4 micro-tiles.
// Smem: Qt[d][q] (persistent), Kt[d][k] (reused as P^T[k][q]), Vs[k][d].
#define FLD 65
#define FLASH_SMEM (3 * 64 * FLD * 4)

__global__ __launch_bounds__(256) void flash_attn_kernel(
    const float* __restrict__ Q, const float* __restrict__ Kg,
    const float* __restrict__ Vg, const int* __restrict__ mask,
    float* __restrict__ Og)
{
    extern __shared__ float sm[];
    float* Qt = sm;                 // [64 d][65] : Qt[d*FLD + q]
    float* Kt = sm + 64 * FLD;      // [64 d][65] : Kt[d*FLD + k]; later P^T[k*FLD + q]
    float* Vs = sm + 2 * 64 * FLD;  // [64 k][65] : Vs[k*FLD + d]

    const int tid = threadIdx.x;
    const int tx = tid & 15;   // k-cols / dk-cols (4 each)
    const int ty = tid >> 4;   // q-rows (4 each)
    const int q0 = blockIdx.x * 64;
    const int h  = blockIdx.y;
    const int b  = blockIdx.z;

    const float* qb = Q  + (size_t)b * SEQ * DMODEL + h * DK;
    const float* kb = Kg + (size_t)b * SEQ * DMODEL + h * DK;
    const float* vb = Vg + (size_t)b * SEQ * DMODEL + h * DK;
    const int*   mb = mask + b * SEQ;

    // Load Q tile transposed (conflict-free: consecutive lanes -> consecutive d)
    for (int i = tid; i < 64 * 64; i += 256) {
        int r = i >> 6, d = i & 63;
        Qt[d * FLD + r] = qb[(size_t)(q0 + r) * DMODEL + d];
    }

    float m_i[4], l_i[4], o[4][4];
#pragma unroll
    for (int i = 0; i < 4; i++) {
        m_i[i] = -1e30f; l_i[i] = 0.f;
#pragma unroll
        for (int j = 0; j < 4; j++) o[i][j] = 0.f;
    }
    __syncthreads();

    for (int kt = 0; kt < SEQ; kt += 64) {
        // Stage K (transposed) and V tiles
        for (int i = tid; i < 64 * 64; i += 256) {
            int r = i >> 6, d = i & 63;
            float kvK = kb[(size_t)(kt + r) * DMODEL + d];
            float kvV = vb[(size_t)(kt + r) * DMODEL + d];
            Kt[d * FLD + r] = kvK;
            Vs[r * FLD + d] = kvV;
        }
        __syncthreads();

        // S = Q @ K^T (4x4 per thread)
        float s[4][4];
#pragma unroll
        for (int i = 0; i < 4; i++)
#pragma unroll
            for (int j = 0; j < 4; j++) s[i][j] = 0.f;

#pragma unroll 4
        for (int d = 0; d < 64; d++) {
            float a[4], bb[4];
#pragma unroll
            for (int i = 0; i < 4; i++) a[i]  = Qt[d * FLD + ty * 4 + i];
#pragma unroll
            for (int j = 0; j < 4; j++) bb[j] = Kt[d * FLD + tx * 4 + j];
#pragma unroll
            for (int i = 0; i < 4; i++)
#pragma unroll
                for (int j = 0; j < 4; j++) s[i][j] += a[i] * bb[j];
        }

        // scale + mask
        const float scale = 0.125f;  // 1/sqrt(64)
        int kcb = kt + tx * 4;
        int mk[4];
#pragma unroll
        for (int j = 0; j < 4; j++) mk[j] = mb[kcb + j];
#pragma unroll
        for (int i = 0; i < 4; i++)
#pragma unroll
            for (int j = 0; j < 4; j++)
                s[i][j] = (mk[j] == 0) ? -1e30f : s[i][j] * scale;

        // online softmax update (reduce across 16 lanes sharing same q-rows)
#pragma unroll
        for (int i = 0; i < 4; i++) {
            float mx = s[i][0];
#pragma unroll
            for (int j = 1; j < 4; j++) mx = fmaxf(mx, s[i][j]);
#pragma unroll
            for (int off = 8; off >= 1; off >>= 1)
                mx = fmaxf(mx, __shfl_xor_sync(0xffffffffu, mx, off));
            float mnew = fmaxf(m_i[i], mx);
            float corr = __expf(m_i[i] - mnew);
            m_i[i] = mnew;
            l_i[i] *= corr;
#pragma unroll
            for (int j = 0; j < 4; j++) o[i][j] *= corr;
            float rs = 0.f;
#pragma unroll
            for (int j = 0; j < 4; j++) {
                float p = __expf(s[i][j] - mnew);
                s[i][j] = p;
                rs += p;
            }
#pragma unroll
            for (int off = 8; off >= 1; off >>= 1)
                rs += __shfl_xor_sync(0xffffffffu, rs, off);
            l_i[i] += rs;
        }

        __syncthreads();  // all reads of Kt done; reuse as P^T
#pragma unroll
        for (int j = 0; j < 4; j++)
#pragma unroll
            for (int i = 0; i < 4; i++)
                Kt[(tx * 4 + j) * FLD + ty * 4 + i] = s[i][j];
        __syncthreads();

        // O += P @ V
#pragma unroll 4
        for (int kc = 0; kc < 64; kc++) {
            float a[4], bb[4];
#pragma unroll
            for (int i = 0; i < 4; i++) a[i]  = Kt[kc * FLD + ty * 4 + i];
#pragma unroll
            for (int j = 0; j < 4; j++) bb[j] = Vs[kc * FLD + tx * 4 + j];
#pragma unroll
            for (int i = 0; i < 4; i++)
#pragma unroll
                for (int j = 0; j < 4; j++) o[i][j] += a[i] * bb[j];
        }
        __syncthreads();  // before next tile overwrites Kt/Vs
    }

    // normalize + write [B,S,D] layout
#pragma unroll
    for (int i = 0; i < 4; i++) {
        float inv = 1.f / l_i[i];
        size_t row = (size_t)b * SEQ + q0 + ty * 4 + i;
#pragma unroll
        for (int j = 0; j < 4; j++)
            Og[row * DMODEL + h * DK + tx * 4 + j] = o[i][j] * inv;
    }
}

// ---------------- launcher ---------------------------------------------------
extern "C" void kernel_launch(void* const* d_in, const int* in_sizes, int n_in,
                              void* d_out, int out_size)
{
    const float* x    = (const float*)d_in[0];
    const int*   mask = (const int*)  d_in[1];
    const float* Wq = (const float*)d_in[2];
    const float* bq = (const float*)d_in[3];
    const float* Wk = (const float*)d_in[4];
    const float* bk = (const float*)d_in[5];
    const float* Wv = (const float*)d_in[6];
    const float* bv = (const float*)d_in[7];
    const float* Wo = (const float*)d_in[8];
    const float* bo = (const float*)d_in[9];
    float* out = (float*)d_out;

    float *pq, *pk, *pv, *pa;
    cudaGetSymbolAddress((void**)&pq, g_q);
    cudaGetSymbolAddress((void**)&pk, g_k);
    cudaGetSymbolAddress((void**)&pv, g_v);
    cudaGetSymbolAddress((void**)&pa, g_attn);

    cudaFuncSetAttribute(flash_attn_kernel,
                         cudaFuncAttributeMaxDynamicSharedMemorySize, FLASH_SMEM);

    dim3 ggrid(DMODEL / 64, MROWS / 128);

    gemm_nt_kernel<<<ggrid, 256>>>(x, Wq, bq, pq, MROWS, DMODEL, DMODEL);
    gemm_nt_kernel<<<ggrid, 256>>>(x, Wk, bk, pk, MROWS, DMODEL, DMODEL);
    gemm_nt_kernel<<<ggrid, 256>>>(x, Wv, bv, pv, MROWS, DMODEL, DMODEL);

    dim3 fgrid(SEQ / 64, NHEADS, BATCH);
    flash_attn_kernel<<<fgrid, 256, FLASH_SMEM>>>(pq, pk, pv, mask, pa);

    gemm_nt_kernel<<<ggrid, 256>>>(pa, Wo, bo, out, MROWS, DMODEL, DMODEL);
}

// round 3
// speedup vs baseline: 1.2868x; 1.2868x over previous
#include <cuda_runtime.h>
#include <cuda_bf16.h>
#include <math.h>
#include <cstdint>

// Problem constants
#define BATCH 4
#define SEQ   2048
#define DMODEL 1024
#define NHEADS 16
#define DK    64
#define MROWS (BATCH * SEQ)   // 8192
#define G_K 1024
#define G_N 1024

// ---------------- scratch (static device globals; no runtime allocation) ----
__device__ float g_q[MROWS * DMODEL];
__device__ float g_k[MROWS * DMODEL];
__device__ float g_v[MROWS * DMODEL];
__device__ float g_attn[MROWS * DMODEL];
__device__ __nv_bfloat16 g_xh[MROWS * DMODEL];
__device__ __nv_bfloat16 g_xl[MROWS * DMODEL];
__device__ __nv_bfloat16 g_wh[4][DMODEL * DMODEL];
__device__ __nv_bfloat16 g_wl[4][DMODEL * DMODEL];

// ---------------- helpers ----------------------------------------------------
__device__ __forceinline__ uint32_t smem_to_u32(const void* p) {
    uint32_t a;
    asm("{ .reg .u64 t; cvta.to.shared.u64 t, %1; cvt.u32.u64 %0, t; }" : "=r"(a) : "l"(p));
    return a;
}
__device__ __forceinline__ void ldm_x4(uint32_t* r, uint32_t addr) {
    asm volatile("ldmatrix.sync.aligned.m8n8.x4.shared.b16 {%0,%1,%2,%3}, [%4];"
                 : "=r"(r[0]), "=r"(r[1]), "=r"(r[2]), "=r"(r[3]) : "r"(addr));
}
__device__ __forceinline__ void mma16816(float* c, const uint32_t* a, const uint32_t* b) {
    asm volatile("mma.sync.aligned.m16n8k16.row.col.f32.bf16.bf16.f32 "
                 "{%0,%1,%2,%3}, {%4,%5,%6,%7}, {%8,%9}, {%0,%1,%2,%3};"
                 : "+f"(c[0]), "+f"(c[1]), "+f"(c[2]), "+f"(c[3])
                 : "r"(a[0]), "r"(a[1]), "r"(a[2]), "r"(a[3]), "r"(b[0]), "r"(b[1]));
}

// ---------------- split fp32 -> bf16 hi + bf16 lo ----------------------------
__global__ __launch_bounds__(256) void split_kernel(
    const float* __restrict__ in, __nv_bfloat16* __restrict__ hi,
    __nv_bfloat16* __restrict__ lo, int n4)
{
    int i = blockIdx.x * blockDim.x + threadIdx.x;
    if (i >= n4) return;
    float4 x = ((const float4*)in)[i];
    __nv_bfloat16 h0 = __float2bfloat16(x.x);
    __nv_bfloat16 h1 = __float2bfloat16(x.y);
    __nv_bfloat16 h2 = __float2bfloat16(x.z);
    __nv_bfloat16 h3 = __float2bfloat16(x.w);
    __nv_bfloat16 l0 = __float2bfloat16(x.x - __bfloat162float(h0));
    __nv_bfloat16 l1 = __float2bfloat16(x.y - __bfloat162float(h1));
    __nv_bfloat16 l2 = __float2bfloat16(x.z - __bfloat162float(h2));
    __nv_bfloat16 l3 = __float2bfloat16(x.w - __bfloat162float(h3));
    ((__nv_bfloat162*)hi)[2 * i + 0] = __nv_bfloat162(h0, h1);
    ((__nv_bfloat162*)hi)[2 * i + 1] = __nv_bfloat162(h2, h3);
    ((__nv_bfloat162*)lo)[2 * i + 0] = __nv_bfloat162(l0, l1);
    ((__nv_bfloat162*)lo)[2 * i + 1] = __nv_bfloat162(l2, l3);
}

// ---------------- HMMA GEMM: C[M,N] = (Ah+Al) @ (Bh+Bl)^T + bias -------------
// 128x128 block tile, K-chunk 64, 8 warps (2 m x 4 n), warp tile 64x32.
// Smem per matrix: 128 rows x 64 bf16 (128B) with XOR-16B swizzle.
#define GSM 16384
#define GEMM_SMEM (4 * GSM)

__global__ __launch_bounds__(256, 1) void gemm_hmma(
    const __nv_bfloat16* __restrict__ Ah, const __nv_bfloat16* __restrict__ Al,
    const __nv_bfloat16* __restrict__ Bh, const __nv_bfloat16* __restrict__ Bl,
    const float* __restrict__ bias, float* __restrict__ C)
{
    extern __shared__ __align__(1024) char smem[];
    char* sAh = smem;
    char* sAl = smem + GSM;
    char* sBh = smem + 2 * GSM;
    char* sBl = smem + 3 * GSM;

    const int tid  = threadIdx.x;
    const int lane = tid & 31;
    const int wid  = tid >> 5;
    const int m0 = blockIdx.y * 128;
    const int n0 = blockIdx.x * 128;
    const int warp_m = (wid & 1) * 64;
    const int warp_n = (wid >> 1) * 32;

    const uint32_t uAh = smem_to_u32(sAh);
    const uint32_t uAl = smem_to_u32(sAl);
    const uint32_t uBh = smem_to_u32(sBh);
    const uint32_t uBl = smem_to_u32(sBl);

    float acc[4][4][4];
#pragma unroll
    for (int i = 0; i < 4; i++)
#pragma unroll
        for (int j = 0; j < 4; j++)
#pragma unroll
            for (int f = 0; f < 4; f++) acc[i][j][f] = 0.f;

    // ldmatrix lane roles
    const int rowA = (lane & 15);          // + warp_m + mi*16
    const int colA = (lane >> 4);          // + ks*2
    const int rowB = (lane & 7) + ((lane >> 4) << 3);   // + warp_n + nj2*16
    const int colB = ((lane >> 3) & 1);    // + ks*2

    // staging role: 1024 uint4 per matrix, 4 per thread
    for (int kt = 0; kt < G_K / 64; kt++) {
        const int k0 = kt * 64;
#pragma unroll
        for (int it = 0; it < 4; it++) {
            int c = tid + it * 256;
            int r = c >> 3, c16 = c & 7;
            uint32_t sw = (uint32_t)(r * 128 + ((c16 ^ (r & 7)) << 4));
            size_t aoff = (size_t)(m0 + r) * G_K + k0 + c16 * 8;
            size_t boff = (size_t)(n0 + r) * G_K + k0 + c16 * 8;
            *(uint4*)(sAh + sw) = *(const uint4*)(Ah + aoff);
            *(uint4*)(sAl + sw) = *(const uint4*)(Al + aoff);
            *(uint4*)(sBh + sw) = *(const uint4*)(Bh + boff);
            *(uint4*)(sBl + sw) = *(const uint4*)(Bl + boff);
        }
        __syncthreads();

#pragma unroll
        for (int ks = 0; ks < 4; ks++) {
            uint32_t fAh[4][4], fAl[4][4], fBh[2][4], fBl[2][4];
#pragma unroll
            for (int mi = 0; mi < 4; mi++) {
                int r = warp_m + mi * 16 + rowA;
                uint32_t off = (uint32_t)(r * 128 + (((ks * 2 + colA) ^ (r & 7)) << 4));
                ldm_x4(fAh[mi], uAh + off);
                ldm_x4(fAl[mi], uAl + off);
            }
#pragma unroll
            for (int nj2 = 0; nj2 < 2; nj2++) {
                int r = warp_n + nj2 * 16 + rowB;
                uint32_t off = (uint32_t)(r * 128 + (((ks * 2 + colB) ^ (r & 7)) << 4));
                ldm_x4(fBh[nj2], uBh + off);
                ldm_x4(fBl[nj2], uBl + off);
            }
#pragma unroll
            for (int mi = 0; mi < 4; mi++)
#pragma unroll
                for (int nj = 0; nj < 4; nj++) {
                    const uint32_t* bh = &fBh[nj >> 1][(nj & 1) * 2];
                    const uint32_t* bl = &fBl[nj >> 1][(nj & 1) * 2];
                    mma16816(acc[mi][nj], fAh[mi], bh);
                    mma16816(acc[mi][nj], fAh[mi], bl);
                    mma16816(acc[mi][nj], fAl[mi], bh);
                }
        }
        __syncthreads();
    }

    // Epilogue: c0,c1 -> (m=lane/4, n=2*(lane%4)+{0,1}); c2,c3 -> m+8
#pragma unroll
    for (int mi = 0; mi < 4; mi++) {
#pragma unroll
        for (int nj = 0; nj < 4; nj++) {
            int n = n0 + warp_n + nj * 8 + (lane & 3) * 2;
            float2 bv = *(const float2*)(bias + n);
            int r0 = m0 + warp_m + mi * 16 + (lane >> 2);
            float2 o0 = make_float2(acc[mi][nj][0] + bv.x, acc[mi][nj][1] + bv.y);
            float2 o1 = make_float2(acc[mi][nj][2] + bv.x, acc[mi][nj][3] + bv.y);
            *(float2*)(C + (size_t)r0 * G_N + n)       = o0;
            *(float2*)(C + (size_t)(r0 + 8) * G_N + n) = o1;
        }
    }
}

// ---------------- Flash attention (fp32, online softmax) --------------------
#define FLD 65
#define FLASH_SMEM (3 * 64 * FLD * 4)

__global__ __launch_bounds__(256) void flash_attn_kernel(
    const float* __restrict__ Q, const float* __restrict__ Kg,
    const float* __restrict__ Vg, const int* __restrict__ mask,
    float* __restrict__ Og)
{
    extern __shared__ float sm[];
    float* Qt = sm;                 // [64 d][65]
    float* Kt = sm + 64 * FLD;      // [64 d][65]; later P^T
    float* Vs = sm + 2 * 64 * FLD;  // [64 k][65]

    const int tid = threadIdx.x;
    const int tx = tid & 15;
    const int ty = tid >> 4;
    const int q0 = blockIdx.x * 64;
    const int h  = blockIdx.y;
    const int b  = blockIdx.z;

    const float* qb = Q  + (size_t)b * SEQ * DMODEL + h * DK;
    const float* kb = Kg + (size_t)b * SEQ * DMODEL + h * DK;
    const float* vb = Vg + (size_t)b * SEQ * DMODEL + h * DK;
    const int*   mb = mask + b * SEQ;

    for (int i = tid; i < 64 * 64; i += 256) {
        int r = i >> 6, d = i & 63;
        Qt[d * FLD + r] = qb[(size_t)(q0 + r) * DMODEL + d];
    }

    float m_i[4], l_i[4], o[4][4];
#pragma unroll
    for (int i = 0; i < 4; i++) {
        m_i[i] = -1e30f; l_i[i] = 0.f;
#pragma unroll
        for (int j = 0; j < 4; j++) o[i][j] = 0.f;
    }
    __syncthreads();

    for (int kt = 0; kt < SEQ; kt += 64) {
        for (int i = tid; i < 64 * 64; i += 256) {
            int r = i >> 6, d = i & 63;
            Kt[d * FLD + r] = kb[(size_t)(kt + r) * DMODEL + d];
            Vs[r * FLD + d] = vb[(size_t)(kt + r) * DMODEL + d];
        }
        __syncthreads();

        float s[4][4];
#pragma unroll
        for (int i = 0; i < 4; i++)
#pragma unroll
            for (int j = 0; j < 4; j++) s[i][j] = 0.f;

#pragma unroll 4
        for (int d = 0; d < 64; d++) {
            float a[4], bb[4];
#pragma unroll
            for (int i = 0; i < 4; i++) a[i]  = Qt[d * FLD + ty * 4 + i];
#pragma unroll
            for (int j = 0; j < 4; j++) bb[j] = Kt[d * FLD + tx * 4 + j];
#pragma unroll
            for (int i = 0; i < 4; i++)
#pragma unroll
                for (int j = 0; j < 4; j++) s[i][j] += a[i] * bb[j];
        }

        const float scale = 0.125f;
        int kcb = kt + tx * 4;
        int mk[4];
#pragma unroll
        for (int j = 0; j < 4; j++) mk[j] = mb[kcb + j];
#pragma unroll
        for (int i = 0; i < 4; i++)
#pragma unroll
            for (int j = 0; j < 4; j++)
                s[i][j] = (mk[j] == 0) ? -1e30f : s[i][j] * scale;

#pragma unroll
        for (int i = 0; i < 4; i++) {
            float mx = s[i][0];
#pragma unroll
            for (int j = 1; j < 4; j++) mx = fmaxf(mx, s[i][j]);
#pragma unroll
            for (int off = 8; off >= 1; off >>= 1)
                mx = fmaxf(mx, __shfl_xor_sync(0xffffffffu, mx, off));
            float mnew = fmaxf(m_i[i], mx);
            float corr = __expf(m_i[i] - mnew);
            m_i[i] = mnew;
            l_i[i] *= corr;
#pragma unroll
            for (int j = 0; j < 4; j++) o[i][j] *= corr;
            float rs = 0.f;
#pragma unroll
            for (int j = 0; j < 4; j++) {
                float p = __expf(s[i][j] - mnew);
                s[i][j] = p;
                rs += p;
            }
#pragma unroll
            for (int off = 8; off >= 1; off >>= 1)
                rs += __shfl_xor_sync(0xffffffffu, rs, off);
            l_i[i] += rs;
        }

        __syncthreads();
#pragma unroll
        for (int j = 0; j < 4; j++)
#pragma unroll
            for (int i = 0; i < 4; i++)
                Kt[(tx * 4 + j) * FLD + ty * 4 + i] = s[i][j];
        __syncthreads();

#pragma unroll 4
        for (int kc = 0; kc < 64; kc++) {
            float a[4], bb[4];
#pragma unroll
            for (int i = 0; i < 4; i++) a[i]  = Kt[kc * FLD + ty * 4 + i];
#pragma unroll
            for (int j = 0; j < 4; j++) bb[j] = Vs[kc * FLD + tx * 4 + j];
#pragma unroll
            for (int i = 0; i < 4; i++)
#pragma unroll
                for (int j = 0; j < 4; j++) o[i][j] += a[i] * bb[j];
        }
        __syncthreads();
    }

#pragma unroll
    for (int i = 0; i < 4; i++) {
        float inv = 1.f / l_i[i];
        size_t row = (size_t)b * SEQ + q0 + ty * 4 + i;
#pragma unroll
        for (int j = 0; j < 4; j++)
            Og[row * DMODEL + h * DK + tx * 4 + j] = o[i][j] * inv;
    }
}

// ---------------- launcher ---------------------------------------------------
extern "C" void kernel_launch(void* const* d_in, const int* in_sizes, int n_in,
                              void* d_out, int out_size)
{
    const float* x    = (const float*)d_in[0];
    const int*   mask = (const int*)  d_in[1];
    const float* Wq = (const float*)d_in[2];
    const float* bq = (const float*)d_in[3];
    const float* Wk = (const float*)d_in[4];
    const float* bk = (const float*)d_in[5];
    const float* Wv = (const float*)d_in[6];
    const float* bv = (const float*)d_in[7];
    const float* Wo = (const float*)d_in[8];
    const float* bo = (const float*)d_in[9];
    float* out = (float*)d_out;

    float *pq, *pk, *pv, *pa;
    __nv_bfloat16 *xh, *xl, *wh, *wl;
    cudaGetSymbolAddress((void**)&pq, g_q);
    cudaGetSymbolAddress((void**)&pk, g_k);
    cudaGetSymbolAddress((void**)&pv, g_v);
    cudaGetSymbolAddress((void**)&pa, g_attn);
    cudaGetSymbolAddress((void**)&xh, g_xh);
    cudaGetSymbolAddress((void**)&xl, g_xl);
    cudaGetSymbolAddress((void**)&wh, g_wh);
    cudaGetSymbolAddress((void**)&wl, g_wl);

    cudaFuncSetAttribute(flash_attn_kernel,
                         cudaFuncAttributeMaxDynamicSharedMemorySize, FLASH_SMEM);
    cudaFuncSetAttribute(gemm_hmma,
                         cudaFuncAttributeMaxDynamicSharedMemorySize, GEMM_SMEM);

    const int WSZ = DMODEL * DMODEL;            // 1M elems
    const int n4x = MROWS * DMODEL / 4;         // 2M float4
    const int n4w = WSZ / 4;                    // 256K float4

    split_kernel<<<n4x / 256, 256>>>(x, xh, xl, n4x);
    split_kernel<<<n4w / 256, 256>>>(Wq, wh + 0 * WSZ, wl + 0 * WSZ, n4w);
    split_kernel<<<n4w / 256, 256>>>(Wk, wh + 1 * WSZ, wl + 1 * WSZ, n4w);
    split_kernel<<<n4w / 256, 256>>>(Wv, wh + 2 * WSZ, wl + 2 * WSZ, n4w);
    split_kernel<<<n4w / 256, 256>>>(Wo, wh + 3 * WSZ, wl + 3 * WSZ, n4w);

    dim3 ggrid(G_N / 128, MROWS / 128);   // (8, 64)
    gemm_hmma<<<ggrid, 256, GEMM_SMEM>>>(xh, xl, wh + 0 * WSZ, wl + 0 * WSZ, bq, pq);
    gemm_hmma<<<ggrid, 256, GEMM_SMEM>>>(xh, xl, wh + 1 * WSZ, wl + 1 * WSZ, bk, pk);
    gemm_hmma<<<ggrid, 256, GEMM_SMEM>>>(xh, xl, wh + 2 * WSZ, wl + 2 * WSZ, bv, pv);

    dim3 fgrid(SEQ / 64, NHEADS, BATCH);
    flash_attn_kernel<<<fgrid, 256, FLASH_SMEM>>>(pq, pk, pv, mask, pa);

    split_kernel<<<n4x / 256, 256>>>(pa, xh, xl, n4x);
    gemm_hmma<<<ggrid, 256, GEMM_SMEM>>>(xh, xl, wh + 3 * WSZ, wl + 3 * WSZ, bo, out);
}

// round 4
// speedup vs baseline: 2.7165x; 2.1111x over previous
#include <cuda_runtime.h>
#include <cuda_bf16.h>
#include <math.h>
#include <cstdint>

// Problem constants
#define BATCH 4
#define SEQ   2048
#define DMODEL 1024
#define NHEADS 16
#define DK    64
#define MROWS (BATCH * SEQ)   // 8192
#define G_K 1024
#define G_N 1024

// ---------------- scratch (static device globals; no runtime allocation) ----
__device__ __nv_bfloat16 g_xh[MROWS * DMODEL];
__device__ __nv_bfloat16 g_xl[MROWS * DMODEL];
__device__ __nv_bfloat16 g_wh[4][DMODEL * DMODEL];
__device__ __nv_bfloat16 g_wl[4][DMODEL * DMODEL];
__device__ __nv_bfloat16 g_qh[MROWS * DMODEL];
__device__ __nv_bfloat16 g_ql[MROWS * DMODEL];
__device__ __nv_bfloat16 g_kh[MROWS * DMODEL];
__device__ __nv_bfloat16 g_kl[MROWS * DMODEL];
__device__ __nv_bfloat16 g_vh[MROWS * DMODEL];
__device__ __nv_bfloat16 g_vl[MROWS * DMODEL];

// ---------------- helpers ----------------------------------------------------
__device__ __forceinline__ uint32_t smem_to_u32(const void* p) {
    uint32_t a;
    asm("{ .reg .u64 t; cvta.to.shared.u64 t, %1; cvt.u32.u64 %0, t; }" : "=r"(a) : "l"(p));
    return a;
}
__device__ __forceinline__ void ldm_x4(uint32_t* r, uint32_t addr) {
    asm volatile("ldmatrix.sync.aligned.m8n8.x4.shared.b16 {%0,%1,%2,%3}, [%4];"
                 : "=r"(r[0]), "=r"(r[1]), "=r"(r[2]), "=r"(r[3]) : "r"(addr));
}
__device__ __forceinline__ void ldm_x4_t(uint32_t* r, uint32_t addr) {
    asm volatile("ldmatrix.sync.aligned.m8n8.x4.trans.shared.b16 {%0,%1,%2,%3}, [%4];"
                 : "=r"(r[0]), "=r"(r[1]), "=r"(r[2]), "=r"(r[3]) : "r"(addr));
}
__device__ __forceinline__ void mma16816(float* c, const uint32_t* a, const uint32_t* b) {
    asm volatile("mma.sync.aligned.m16n8k16.row.col.f32.bf16.bf16.f32 "
                 "{%0,%1,%2,%3}, {%4,%5,%6,%7}, {%8,%9}, {%0,%1,%2,%3};"
                 : "+f"(c[0]), "+f"(c[1]), "+f"(c[2]), "+f"(c[3])
                 : "r"(a[0]), "r"(a[1]), "r"(a[2]), "r"(a[3]), "r"(b[0]), "r"(b[1]));
}
// pack two fp32 -> bf16x2 (lo in low half)
__device__ __forceinline__ uint32_t pack_bf16x2(float lo, float hi) {
    uint32_t r;
    asm("cvt.rn.satfinite.bf16x2.f32 %0, %1, %2;" : "=r"(r) : "f"(hi), "f"(lo));
    return r;
}
// fast 2^x on the FMA pipe (no MUFU). rel err ~2e-6. valid for x <= ~0.5
__device__ __forceinline__ float exp2_fast(float x) {
    x = fmaxf(x, -100.f);
    float t = x + 12582912.f;                  // round-to-nearest-int magic
    int   n = __float_as_int(t) - 0x4B400000;
    float f = x - (t - 12582912.f);            // f in [-0.5, 0.5]
    float p = 0.0013333558f;
    p = fmaf(p, f, 0.0096181291f);
    p = fmaf(p, f, 0.0555041087f);
    p = fmaf(p, f, 0.2402265069f);
    p = fmaf(p, f, 0.6931471806f);
    p = fmaf(p, f, 1.0f);
    return __int_as_float(__float_as_int(p) + (n << 23));
}

// ---------------- split fp32 -> bf16 hi + bf16 lo ----------------------------
__global__ __launch_bounds__(256) void split_kernel(
    const float* __restrict__ in, __nv_bfloat16* __restrict__ hi,
    __nv_bfloat16* __restrict__ lo, int n4)
{
    int i = blockIdx.x * blockDim.x + threadIdx.x;
    if (i >= n4) return;
    float4 x = ((const float4*)in)[i];
    __nv_bfloat16 h0 = __float2bfloat16(x.x);
    __nv_bfloat16 h1 = __float2bfloat16(x.y);
    __nv_bfloat16 h2 = __float2bfloat16(x.z);
    __nv_bfloat16 h3 = __float2bfloat16(x.w);
    __nv_bfloat16 l0 = __float2bfloat16(x.x - __bfloat162float(h0));
    __nv_bfloat16 l1 = __float2bfloat16(x.y - __bfloat162float(h1));
    __nv_bfloat16 l2 = __float2bfloat16(x.z - __bfloat162float(h2));
    __nv_bfloat16 l3 = __float2bfloat16(x.w - __bfloat162float(h3));
    ((__nv_bfloat162*)hi)[2 * i + 0] = __nv_bfloat162(h0, h1);
    ((__nv_bfloat162*)hi)[2 * i + 1] = __nv_bfloat162(h2, h3);
    ((__nv_bfloat162*)lo)[2 * i + 0] = __nv_bfloat162(l0, l1);
    ((__nv_bfloat162*)lo)[2 * i + 1] = __nv_bfloat162(l2, l3);
}

// ---------------- HMMA GEMM: C = (Ah+Al)(Bh+Bl)^T + bias ---------------------
// 128x128 block tile, K-chunk 64, 8 warps (2m x 4n), warp tile 64x32.
// Epilogue: fp32 C (if Co) or bf16 hi/lo split (Ch/Cl).
#define GSM 16384
#define GEMM_SMEM (4 * GSM)

__global__ __launch_bounds__(256, 1) void gemm_hmma(
    const __nv_bfloat16* __restrict__ Ah, const __nv_bfloat16* __restrict__ Al,
    const __nv_bfloat16* __restrict__ Bh, const __nv_bfloat16* __restrict__ Bl,
    const float* __restrict__ bias, float* __restrict__ Co,
    __nv_bfloat16* __restrict__ Ch, __nv_bfloat16* __restrict__ Cl)
{
    extern __shared__ __align__(1024) char smem[];
    char* sAh = smem;
    char* sAl = smem + GSM;
    char* sBh = smem + 2 * GSM;
    char* sBl = smem + 3 * GSM;

    const int tid  = threadIdx.x;
    const int lane = tid & 31;
    const int wid  = tid >> 5;
    const int m0 = blockIdx.y * 128;
    const int n0 = blockIdx.x * 128;
    const int warp_m = (wid & 1) * 64;
    const int warp_n = (wid >> 1) * 32;

    const uint32_t uAh = smem_to_u32(sAh);
    const uint32_t uAl = smem_to_u32(sAl);
    const uint32_t uBh = smem_to_u32(sBh);
    const uint32_t uBl = smem_to_u32(sBl);

    float acc[4][4][4];
#pragma unroll
    for (int i = 0; i < 4; i++)
#pragma unroll
        for (int j = 0; j < 4; j++)
#pragma unroll
            for (int f = 0; f < 4; f++) acc[i][j][f] = 0.f;

    const int rowA = (lane & 15);
    const int colA = (lane >> 4);
    const int rowB = (lane & 7) + ((lane >> 4) << 3);
    const int colB = ((lane >> 3) & 1);

    for (int kt = 0; kt < G_K / 64; kt++) {
        const int k0 = kt * 64;
#pragma unroll
        for (int it = 0; it < 4; it++) {
            int c = tid + it * 256;
            int r = c >> 3, c16 = c & 7;
            uint32_t sw = (uint32_t)(r * 128 + ((c16 ^ (r & 7)) << 4));
            size_t aoff = (size_t)(m0 + r) * G_K + k0 + c16 * 8;
            size_t boff = (size_t)(n0 + r) * G_K + k0 + c16 * 8;
            *(uint4*)(sAh + sw) = *(const uint4*)(Ah + aoff);
            *(uint4*)(sAl + sw) = *(const uint4*)(Al + aoff);
            *(uint4*)(sBh + sw) = *(const uint4*)(Bh + boff);
            *(uint4*)(sBl + sw) = *(const uint4*)(Bl + boff);
        }
        __syncthreads();

#pragma unroll
        for (int ks = 0; ks < 4; ks++) {
            uint32_t fAh[4][4], fAl[4][4], fBh[2][4], fBl[2][4];
#pragma unroll
            for (int mi = 0; mi < 4; mi++) {
                int r = warp_m + mi * 16 + rowA;
                uint32_t off = (uint32_t)(r * 128 + (((ks * 2 + colA) ^ (r & 7)) << 4));
                ldm_x4(fAh[mi], uAh + off);
                ldm_x4(fAl[mi], uAl + off);
            }
#pragma unroll
            for (int nj2 = 0; nj2 < 2; nj2++) {
                int r = warp_n + nj2 * 16 + rowB;
                uint32_t off = (uint32_t)(r * 128 + (((ks * 2 + colB) ^ (r & 7)) << 4));
                ldm_x4(fBh[nj2], uBh + off);
                ldm_x4(fBl[nj2], uBl + off);
            }
#pragma unroll
            for (int mi = 0; mi < 4; mi++)
#pragma unroll
                for (int nj = 0; nj < 4; nj++) {
                    const uint32_t* bh = &fBh[nj >> 1][(nj & 1) * 2];
                    const uint32_t* bl = &fBl[nj >> 1][(nj & 1) * 2];
                    mma16816(acc[mi][nj], fAh[mi], bh);
                    mma16816(acc[mi][nj], fAh[mi], bl);
                    mma16816(acc[mi][nj], fAl[mi], bh);
                }
        }
        __syncthreads();
    }

#pragma unroll
    for (int mi = 0; mi < 4; mi++) {
#pragma unroll
        for (int nj = 0; nj < 4; nj++) {
            int n = n0 + warp_n + nj * 8 + (lane & 3) * 2;
            float2 bv = *(const float2*)(bias + n);
            int r0 = m0 + warp_m + mi * 16 + (lane >> 2);
            float o00 = acc[mi][nj][0] + bv.x, o01 = acc[mi][nj][1] + bv.y;
            float o10 = acc[mi][nj][2] + bv.x, o11 = acc[mi][nj][3] + bv.y;
            if (Co) {
                *(float2*)(Co + (size_t)r0 * G_N + n)       = make_float2(o00, o01);
                *(float2*)(Co + (size_t)(r0 + 8) * G_N + n) = make_float2(o10, o11);
            } else {
                uint32_t h0 = pack_bf16x2(o00, o01);
                __nv_bfloat162 h0v = *(__nv_bfloat162*)&h0;
                uint32_t l0 = pack_bf16x2(o00 - __bfloat162float(h0v.x),
                                          o01 - __bfloat162float(h0v.y));
                uint32_t h1 = pack_bf16x2(o10, o11);
                __nv_bfloat162 h1v = *(__nv_bfloat162*)&h1;
                uint32_t l1 = pack_bf16x2(o10 - __bfloat162float(h1v.x),
                                          o11 - __bfloat162float(h1v.y));
                *(uint32_t*)(Ch + (size_t)r0 * G_N + n)       = h0;
                *(uint32_t*)(Cl + (size_t)r0 * G_N + n)       = l0;
                *(uint32_t*)(Ch + (size_t)(r0 + 8) * G_N + n) = h1;
                *(uint32_t*)(Cl + (size_t)(r0 + 8) * G_N + n) = l1;
            }
        }
    }
}

// ---------------- Flash attention (HMMA, online softmax, fast exp2) ----------
// Block: 128 q-rows x (b, h). 8 warps, each 16 q-rows x all 64 keys of a tile.
// Q frags resident in registers; P stays in registers (C-frag == A-frag layout).
#define FSM_QH 0
#define FSM_QL 16384
#define FSM_KH 32768
#define FSM_KL 40960
#define FSM_VH 49152
#define FSM_VL 57344
#define FSM_MASK 65536
#define FLASH_SMEM (65536 + 256)

__global__ __launch_bounds__(256, 1) void flash_hmma(
    const __nv_bfloat16* __restrict__ Qh_, const __nv_bfloat16* __restrict__ Ql_,
    const __nv_bfloat16* __restrict__ Kh_, const __nv_bfloat16* __restrict__ Kl_,
    const __nv_bfloat16* __restrict__ Vh_, const __nv_bfloat16* __restrict__ Vl_,
    const int* __restrict__ mask,
    __nv_bfloat16* __restrict__ Oh_, __nv_bfloat16* __restrict__ Ol_)
{
    extern __shared__ __align__(1024) char smem[];
    char* sQh = smem + FSM_QH;
    char* sQl = smem + FSM_QL;
    char* sKh = smem + FSM_KH;
    char* sKl = smem + FSM_KL;
    char* sVh = smem + FSM_VH;
    char* sVl = smem + FSM_VL;
    int*  smask = (int*)(smem + FSM_MASK);

    const int tid = threadIdx.x, lane = tid & 31, wid = tid >> 5;
    const int q0 = blockIdx.x * 128;
    const int h  = blockIdx.y;
    const int b  = blockIdx.z;
    const size_t baseQ = ((size_t)b * SEQ + q0) * DMODEL + h * DK;
    const size_t baseK = ((size_t)b * SEQ) * DMODEL + h * DK;

    // ---- stage Q (128 x 64 bf16, hi+lo), load Q frags to registers ----
#pragma unroll
    for (int it = 0; it < 4; it++) {
        int c = tid + it * 256;
        int r = c >> 3, c16 = c & 7;
        uint32_t sw = (uint32_t)(r * 128 + ((c16 ^ (r & 7)) << 4));
        size_t src = baseQ + (size_t)r * DMODEL + c16 * 8;
        *(uint4*)(sQh + sw) = *(const uint4*)(Qh_ + src);
        *(uint4*)(sQl + sw) = *(const uint4*)(Ql_ + src);
    }
    __syncthreads();

    uint32_t fQh[4][4], fQl[4][4];
    {
        const uint32_t uQh = smem_to_u32(sQh), uQl = smem_to_u32(sQl);
        int r = wid * 16 + (lane & 15);
        int colA = lane >> 4;
#pragma unroll
        for (int ks = 0; ks < 4; ks++) {
            uint32_t off = (uint32_t)(r * 128 + (((ks * 2 + colA) ^ (r & 7)) << 4));
            ldm_x4(fQh[ks], uQh + off);
            ldm_x4(fQl[ks], uQl + off);
        }
    }

    float m0 = -1e30f, m1 = -1e30f, l0 = 0.f, l1 = 0.f;
    float oacc[8][4];
#pragma unroll
    for (int d = 0; d < 8; d++)
#pragma unroll
        for (int f = 0; f < 4; f++) oacc[d][f] = 0.f;

    const uint32_t uKh = smem_to_u32(sKh), uKl = smem_to_u32(sKl);
    const uint32_t uVh = smem_to_u32(sVh), uVl = smem_to_u32(sVl);
    const int rowB = (lane & 7) + ((lane >> 4) << 3);
    const int colB = (lane >> 3) & 1;
    const int rT = lane & 15;       // ldmatrix.trans row
    const int cT = lane >> 4;       // ldmatrix.trans col-group

    for (int kt = 0; kt < SEQ / 64; kt++) {
        // ---- stage K, V tiles (hi+lo) + mask ----
#pragma unroll
        for (int it = 0; it < 2; it++) {
            int c = tid + it * 256;
            int r = c >> 3, c16 = c & 7;
            uint32_t sw = (uint32_t)(r * 128 + ((c16 ^ (r & 7)) << 4));
            size_t src = baseK + (size_t)(kt * 64 + r) * DMODEL + c16 * 8;
            *(uint4*)(sKh + sw) = *(const uint4*)(Kh_ + src);
            *(uint4*)(sKl + sw) = *(const uint4*)(Kl_ + src);
            *(uint4*)(sVh + sw) = *(const uint4*)(Vh_ + src);
            *(uint4*)(sVl + sw) = *(const uint4*)(Vl_ + src);
        }
        if (tid < 64) smask[tid] = mask[b * SEQ + kt * 64 + tid];
        __syncthreads();

        // ---- S = Q K^T (3-term hi/lo) ----
        float sacc[8][4];
#pragma unroll
        for (int nj = 0; nj < 8; nj++)
#pragma unroll
            for (int f = 0; f < 4; f++) sacc[nj][f] = 0.f;

#pragma unroll
        for (int ks = 0; ks < 4; ks++) {
            uint32_t fKh[4][4], fKl[4][4];
#pragma unroll
            for (int nj2 = 0; nj2 < 4; nj2++) {
                int r = nj2 * 16 + rowB;
                uint32_t off = (uint32_t)(r * 128 + (((ks * 2 + colB) ^ (r & 7)) << 4));
                ldm_x4(fKh[nj2], uKh + off);
                ldm_x4(fKl[nj2], uKl + off);
            }
#pragma unroll
            for (int nj = 0; nj < 8; nj++) {
                const uint32_t* bh = &fKh[nj >> 1][(nj & 1) * 2];
                const uint32_t* bl = &fKl[nj >> 1][(nj & 1) * 2];
                mma16816(sacc[nj], fQh[ks], bh);
                mma16816(sacc[nj], fQh[ks], bl);
                mma16816(sacc[nj], fQl[ks], bh);
            }
        }

        // ---- online softmax (exp2 on FMA pipe) ----
        const float cs = 0.18033688f;  // 0.125 * log2(e)
        float mx0 = -1e30f, mx1 = -1e30f;
#pragma unroll
        for (int nj = 0; nj < 8; nj++) {
            int col = nj * 8 + 2 * (lane & 3);
            bool ma = smask[col] != 0, mb2 = smask[col + 1] != 0;
            float s0 = ma  ? sacc[nj][0] * cs : -1e30f;
            float s1 = mb2 ? sacc[nj][1] * cs : -1e30f;
            float s2 = ma  ? sacc[nj][2] * cs : -1e30f;
            float s3 = mb2 ? sacc[nj][3] * cs : -1e30f;
            sacc[nj][0] = s0; sacc[nj][1] = s1; sacc[nj][2] = s2; sacc[nj][3] = s3;
            mx0 = fmaxf(mx0, fmaxf(s0, s1));
            mx1 = fmaxf(mx1, fmaxf(s2, s3));
        }
        mx0 = fmaxf(mx0, __shfl_xor_sync(0xffffffffu, mx0, 1));
        mx0 = fmaxf(mx0, __shfl_xor_sync(0xffffffffu, mx0, 2));
        mx1 = fmaxf(mx1, __shfl_xor_sync(0xffffffffu, mx1, 1));
        mx1 = fmaxf(mx1, __shfl_xor_sync(0xffffffffu, mx1, 2));

        float mn0 = fmaxf(m0, mx0), mn1 = fmaxf(m1, mx1);
        float cr0 = exp2_fast(m0 - mn0), cr1 = exp2_fast(m1 - mn1);
        m0 = mn0; m1 = mn1;
        l0 *= cr0; l1 *= cr1;
#pragma unroll
        for (int d = 0; d < 8; d++) {
            oacc[d][0] *= cr0; oacc[d][1] *= cr0;
            oacc[d][2] *= cr1; oacc[d][3] *= cr1;
        }

        uint32_t ph01[8], ph23[8], pl01[8], pl23[8];
        float rs0 = 0.f, rs1 = 0.f;
#pragma unroll
        for (int nj = 0; nj < 8; nj++) {
            float p0 = exp2_fast(sacc[nj][0] - mn0);
            float p1 = exp2_fast(sacc[nj][1] - mn0);
            float p2 = exp2_fast(sacc[nj][2] - mn1);
            float p3 = exp2_fast(sacc[nj][3] - mn1);
            rs0 += p0 + p1; rs1 += p2 + p3;
            uint32_t hA = pack_bf16x2(p0, p1);
            uint32_t hB = pack_bf16x2(p2, p3);
            ph01[nj] = hA; ph23[nj] = hB;
            __nv_bfloat162 hA2 = *(__nv_bfloat162*)&hA;
            __nv_bfloat162 hB2 = *(__nv_bfloat162*)&hB;
            pl01[nj] = pack_bf16x2(p0 - __bfloat162float(hA2.x),
                                   p1 - __bfloat162float(hA2.y));
            pl23[nj] = pack_bf16x2(p2 - __bfloat162float(hB2.x),
                                   p3 - __bfloat162float(hB2.y));
        }
        rs0 += __shfl_xor_sync(0xffffffffu, rs0, 1);
        rs0 += __shfl_xor_sync(0xffffffffu, rs0, 2);
        rs1 += __shfl_xor_sync(0xffffffffu, rs1, 1);
        rs1 += __shfl_xor_sync(0xffffffffu, rs1, 2);
        l0 += rs0; l1 += rs1;

        // ---- O += P V (3-term; P frags direct from registers) ----
#pragma unroll
        for (int kc = 0; kc < 4; kc++) {
            uint32_t aPh[4] = { ph01[2 * kc], ph23[2 * kc], ph01[2 * kc + 1], ph23[2 * kc + 1] };
            uint32_t aPl[4] = { pl01[2 * kc], pl23[2 * kc], pl01[2 * kc + 1], pl23[2 * kc + 1] };
#pragma unroll
            for (int dn = 0; dn < 4; dn++) {
                int r = kc * 16 + rT;
                int c16 = dn * 2 + cT;
                uint32_t off = (uint32_t)(r * 128 + ((c16 ^ (r & 7)) << 4));
                uint32_t tvh[4], tvl[4];
                ldm_x4_t(tvh, uVh + off);
                ldm_x4_t(tvl, uVl + off);
                mma16816(oacc[2 * dn],     aPh, &tvh[0]);
                mma16816(oacc[2 * dn],     aPh, &tvl[0]);
                mma16816(oacc[2 * dn],     aPl, &tvh[0]);
                mma16816(oacc[2 * dn + 1], aPh, &tvh[2]);
                mma16816(oacc[2 * dn + 1], aPh, &tvl[2]);
                mma16816(oacc[2 * dn + 1], aPl, &tvh[2]);
            }
        }
        __syncthreads();
    }

    // ---- epilogue: normalize, split hi/lo, store ----
    float inv0 = 1.f / l0, inv1 = 1.f / l1;
    size_t row0 = (size_t)b * SEQ + q0 + wid * 16 + (lane >> 2);
#pragma unroll
    for (int d = 0; d < 8; d++) {
        int col = h * DK + d * 8 + 2 * (lane & 3);
        float o0 = oacc[d][0] * inv0, o1 = oacc[d][1] * inv0;
        uint32_t hh = pack_bf16x2(o0, o1);
        __nv_bfloat162 h2 = *(__nv_bfloat162*)&hh;
        uint32_t ll = pack_bf16x2(o0 - __bfloat162float(h2.x),
                                  o1 - __bfloat162float(h2.y));
        *(uint32_t*)(Oh_ + row0 * DMODEL + col) = hh;
        *(uint32_t*)(Ol_ + row0 * DMODEL + col) = ll;
        float o2 = oacc[d][2] * inv1, o3 = oacc[d][3] * inv1;
        uint32_t hh2 = pack_bf16x2(o2, o3);
        __nv_bfloat162 h3 = *(__nv_bfloat162*)&hh2;
        uint32_t ll2 = pack_bf16x2(o2 - __bfloat162float(h3.x),
                                   o3 - __bfloat162float(h3.y));
        *(uint32_t*)(Oh_ + (row0 + 8) * DMODEL + col) = hh2;
        *(uint32_t*)(Ol_ + (row0 + 8) * DMODEL + col) = ll2;
    }
}

// ---------------- launcher ---------------------------------------------------
extern "C" void kernel_launch(void* const* d_in, const int* in_sizes, int n_in,
                              void* d_out, int out_size)
{
    const float* x    = (const float*)d_in[0];
    const int*   mask = (const int*)  d_in[1];
    const float* Wq = (const float*)d_in[2];
    const float* bq = (const float*)d_in[3];
    const float* Wk = (const float*)d_in[4];
    const float* bk = (const float*)d_in[5];
    const float* Wv = (const float*)d_in[6];
    const float* bv = (const float*)d_in[7];
    const float* Wo = (const float*)d_in[8];
    const float* bo = (const float*)d_in[9];
    float* out = (float*)d_out;

    __nv_bfloat16 *xh, *xl, *wh, *wl, *qh, *ql, *kh, *kl, *vh, *vl;
    cudaGetSymbolAddress((void**)&xh, g_xh);
    cudaGetSymbolAddress((void**)&xl, g_xl);
    cudaGetSymbolAddress((void**)&wh, g_wh);
    cudaGetSymbolAddress((void**)&wl, g_wl);
    cudaGetSymbolAddress((void**)&qh, g_qh);
    cudaGetSymbolAddress((void**)&ql, g_ql);
    cudaGetSymbolAddress((void**)&kh, g_kh);
    cudaGetSymbolAddress((void**)&kl, g_kl);
    cudaGetSymbolAddress((void**)&vh, g_vh);
    cudaGetSymbolAddress((void**)&vl, g_vl);

    cudaFuncSetAttribute(gemm_hmma,
                         cudaFuncAttributeMaxDynamicSharedMemorySize, GEMM_SMEM);
    cudaFuncSetAttribute(flash_hmma,
                         cudaFuncAttributeMaxDynamicSharedMemorySize, FLASH_SMEM);

    const int WSZ = DMODEL * DMODEL;
    const int n4x = MROWS * DMODEL / 4;
    const int n4w = WSZ / 4;

    split_kernel<<<n4x / 256, 256>>>(x, xh, xl, n4x);
    split_kernel<<<n4w / 256, 256>>>(Wq, wh + 0 * WSZ, wl + 0 * WSZ, n4w);
    split_kernel<<<n4w / 256, 256>>>(Wk, wh + 1 * WSZ, wl + 1 * WSZ, n4w);
    split_kernel<<<n4w / 256, 256>>>(Wv, wh + 2 * WSZ, wl + 2 * WSZ, n4w);
    split_kernel<<<n4w / 256, 256>>>(Wo, wh + 3 * WSZ, wl + 3 * WSZ, n4w);

    dim3 ggrid(G_N / 128, MROWS / 128);   // (8, 64)
    gemm_hmma<<<ggrid, 256, GEMM_SMEM>>>(xh, xl, wh + 0 * WSZ, wl + 0 * WSZ, bq,
                                         nullptr, qh, ql);
    gemm_hmma<<<ggrid, 256, GEMM_SMEM>>>(xh, xl, wh + 1 * WSZ, wl + 1 * WSZ, bk,
                                         nullptr, kh, kl);
    gemm_hmma<<<ggrid, 256, GEMM_SMEM>>>(xh, xl, wh + 2 * WSZ, wl + 2 * WSZ, bv,
                                         nullptr, vh, vl);

    dim3 fgrid(SEQ / 128, NHEADS, BATCH); // (16, 16, 4)
    flash_hmma<<<fgrid, 256, FLASH_SMEM>>>(qh, ql, kh, kl, vh, vl, mask, xh, xl);

    gemm_hmma<<<ggrid, 256, GEMM_SMEM>>>(xh, xl, wh + 3 * WSZ, wl + 3 * WSZ, bo,
                                         out, nullptr, nullptr);
}

// round 5
// speedup vs baseline: 3.4997x; 1.2883x over previous
#include <cuda_runtime.h>
#include <cuda_bf16.h>
#include <math.h>
#include <cstdint>

// Problem constants
#define BATCH 4
#define SEQ   2048
#define DMODEL 1024
#define NHEADS 16
#define DK    64
#define MROWS (BATCH * SEQ)   // 8192
#define G_K 1024
#define G_N 1024

// ---------------- scratch (static device globals; no runtime allocation) ----
__device__ __nv_bfloat16 g_xh[MROWS * DMODEL];
__device__ __nv_bfloat16 g_xl[MROWS * DMODEL];
__device__ __nv_bfloat16 g_wh[4][DMODEL * DMODEL];
__device__ __nv_bfloat16 g_wl[4][DMODEL * DMODEL];
__device__ __nv_bfloat16 g_qh[MROWS * DMODEL];
__device__ __nv_bfloat16 g_ql[MROWS * DMODEL];
__device__ __nv_bfloat16 g_kh[MROWS * DMODEL];
__device__ __nv_bfloat16 g_kl[MROWS * DMODEL];
__device__ __nv_bfloat16 g_vh[MROWS * DMODEL];
__device__ __nv_bfloat16 g_vl[MROWS * DMODEL];

// ---------------- helpers ----------------------------------------------------
__device__ __forceinline__ uint32_t smem_to_u32(const void* p) {
    uint32_t a;
    asm("{ .reg .u64 t; cvta.to.shared.u64 t, %1; cvt.u32.u64 %0, t; }" : "=r"(a) : "l"(p));
    return a;
}
__device__ __forceinline__ void cp16(uint32_t s, const void* g) {
    asm volatile("cp.async.cg.shared.global [%0], [%1], 16;" :: "r"(s), "l"(g));
}
#define CP_COMMIT() asm volatile("cp.async.commit_group;" ::: "memory")
#define CP_WAIT1()  asm volatile("cp.async.wait_group 1;" ::: "memory")
#define CP_WAIT0()  asm volatile("cp.async.wait_group 0;" ::: "memory")

__device__ __forceinline__ void ldm_x4(uint32_t* r, uint32_t addr) {
    asm volatile("ldmatrix.sync.aligned.m8n8.x4.shared.b16 {%0,%1,%2,%3}, [%4];"
                 : "=r"(r[0]), "=r"(r[1]), "=r"(r[2]), "=r"(r[3]) : "r"(addr));
}
__device__ __forceinline__ void ldm_x4_t(uint32_t* r, uint32_t addr) {
    asm volatile("ldmatrix.sync.aligned.m8n8.x4.trans.shared.b16 {%0,%1,%2,%3}, [%4];"
                 : "=r"(r[0]), "=r"(r[1]), "=r"(r[2]), "=r"(r[3]) : "r"(addr));
}
__device__ __forceinline__ void mma16816(float* c, const uint32_t* a, const uint32_t* b) {
    asm volatile("mma.sync.aligned.m16n8k16.row.col.f32.bf16.bf16.f32 "
                 "{%0,%1,%2,%3}, {%4,%5,%6,%7}, {%8,%9}, {%0,%1,%2,%3};"
                 : "+f"(c[0]), "+f"(c[1]), "+f"(c[2]), "+f"(c[3])
                 : "r"(a[0]), "r"(a[1]), "r"(a[2]), "r"(a[3]), "r"(b[0]), "r"(b[1]));
}
__device__ __forceinline__ uint32_t pack_bf16x2(float lo, float hi) {
    uint32_t r;
    asm("cvt.rn.satfinite.bf16x2.f32 %0, %1, %2;" : "=r"(r) : "f"(hi), "f"(lo));
    return r;
}
// fast 2^x on the FMA pipe (no MUFU). rel err ~2e-6.
__device__ __forceinline__ float exp2_fast(float x) {
    x = fmaxf(x, -100.f);
    float t = x + 12582912.f;
    int   n = __float_as_int(t) - 0x4B400000;
    float f = x - (t - 12582912.f);
    float p = 0.0013333558f;
    p = fmaf(p, f, 0.0096181291f);
    p = fmaf(p, f, 0.0555041087f);
    p = fmaf(p, f, 0.2402265069f);
    p = fmaf(p, f, 0.6931471806f);
    p = fmaf(p, f, 1.0f);
    return __int_as_float(__float_as_int(p) + (n << 23));
}

// ---------------- split fp32 -> bf16 hi + bf16 lo ----------------------------
__global__ __launch_bounds__(256) void split_kernel(
    const float* __restrict__ in, __nv_bfloat16* __restrict__ hi,
    __nv_bfloat16* __restrict__ lo, int n4)
{
    int i = blockIdx.x * blockDim.x + threadIdx.x;
    if (i >= n4) return;
    float4 x = ((const float4*)in)[i];
    __nv_bfloat16 h0 = __float2bfloat16(x.x);
    __nv_bfloat16 h1 = __float2bfloat16(x.y);
    __nv_bfloat16 h2 = __float2bfloat16(x.z);
    __nv_bfloat16 h3 = __float2bfloat16(x.w);
    __nv_bfloat16 l0 = __float2bfloat16(x.x - __bfloat162float(h0));
    __nv_bfloat16 l1 = __float2bfloat16(x.y - __bfloat162float(h1));
    __nv_bfloat16 l2 = __float2bfloat16(x.z - __bfloat162float(h2));
    __nv_bfloat16 l3 = __float2bfloat16(x.w - __bfloat162float(h3));
    ((__nv_bfloat162*)hi)[2 * i + 0] = __nv_bfloat162(h0, h1);
    ((__nv_bfloat162*)hi)[2 * i + 1] = __nv_bfloat162(h2, h3);
    ((__nv_bfloat162*)lo)[2 * i + 0] = __nv_bfloat162(l0, l1);
    ((__nv_bfloat162*)lo)[2 * i + 1] = __nv_bfloat162(l2, l3);
}

// ---------------- HMMA GEMM, 2-stage cp.async pipeline -----------------------
// 128x128 block tile, K-chunk 64, 8 warps (2m x 4n), warp tile 64x32.
#define GSM 16384
#define GSTG (4 * GSM)          // 64KB per stage
#define GEMM_SMEM (2 * GSTG)    // 128KB

__device__ __forceinline__ void gemm_prefetch(
    uint32_t us, const __nv_bfloat16* __restrict__ Ah,
    const __nv_bfloat16* __restrict__ Al, const __nv_bfloat16* __restrict__ Bh,
    const __nv_bfloat16* __restrict__ Bl, int m0, int n0, int k0, int tid)
{
#pragma unroll
    for (int it = 0; it < 4; it++) {
        int c = tid + it * 256;
        int r = c >> 3, c16 = c & 7;
        uint32_t sw = (uint32_t)(r * 128 + ((c16 ^ (r & 7)) << 4));
        size_t aoff = (size_t)(m0 + r) * G_K + k0 + c16 * 8;
        size_t boff = (size_t)(n0 + r) * G_K + k0 + c16 * 8;
        cp16(us + sw,           Ah + aoff);
        cp16(us + GSM + sw,     Al + aoff);
        cp16(us + 2 * GSM + sw, Bh + boff);
        cp16(us + 3 * GSM + sw, Bl + boff);
    }
}

__global__ __launch_bounds__(256, 1) void gemm_hmma(
    const __nv_bfloat16* __restrict__ Ah, const __nv_bfloat16* __restrict__ Al,
    const __nv_bfloat16* __restrict__ Bh, const __nv_bfloat16* __restrict__ Bl,
    const float* __restrict__ bias, float* __restrict__ Co,
    __nv_bfloat16* __restrict__ Ch, __nv_bfloat16* __restrict__ Cl)
{
    extern __shared__ __align__(1024) char smem[];
    const uint32_t u0 = smem_to_u32(smem);

    const int tid  = threadIdx.x;
    const int lane = tid & 31;
    const int wid  = tid >> 5;
    const int m0 = blockIdx.y * 128;
    const int n0 = blockIdx.x * 128;
    const int warp_m = (wid & 1) * 64;
    const int warp_n = (wid >> 1) * 32;

    float acc[4][4][4];
#pragma unroll
    for (int i = 0; i < 4; i++)
#pragma unroll
        for (int j = 0; j < 4; j++)
#pragma unroll
            for (int f = 0; f < 4; f++) acc[i][j][f] = 0.f;

    const int rowA = (lane & 15);
    const int colA = (lane >> 4);
    const int rowB = (lane & 7) + ((lane >> 4) << 3);
    const int colB = ((lane >> 3) & 1);

    gemm_prefetch(u0, Ah, Al, Bh, Bl, m0, n0, 0, tid);
    CP_COMMIT();

    const int NT = G_K / 64;  // 16
    for (int kt = 0; kt < NT; kt++) {
        const uint32_t us = u0 + (uint32_t)(kt & 1) * GSTG;
        if (kt + 1 < NT) {
            gemm_prefetch(u0 + (uint32_t)((kt + 1) & 1) * GSTG,
                          Ah, Al, Bh, Bl, m0, n0, (kt + 1) * 64, tid);
            CP_COMMIT();
            CP_WAIT1();
        } else {
            CP_WAIT0();
        }
        __syncthreads();

        const uint32_t uAh = us, uAl = us + GSM, uBh = us + 2 * GSM, uBl = us + 3 * GSM;
#pragma unroll
        for (int ks = 0; ks < 4; ks++) {
            uint32_t fAh[4][4], fAl[4][4], fBh[2][4], fBl[2][4];
#pragma unroll
            for (int mi = 0; mi < 4; mi++) {
                int r = warp_m + mi * 16 + rowA;
                uint32_t off = (uint32_t)(r * 128 + (((ks * 2 + colA) ^ (r & 7)) << 4));
                ldm_x4(fAh[mi], uAh + off);
                ldm_x4(fAl[mi], uAl + off);
            }
#pragma unroll
            for (int nj2 = 0; nj2 < 2; nj2++) {
                int r = warp_n + nj2 * 16 + rowB;
                uint32_t off = (uint32_t)(r * 128 + (((ks * 2 + colB) ^ (r & 7)) << 4));
                ldm_x4(fBh[nj2], uBh + off);
                ldm_x4(fBl[nj2], uBl + off);
            }
#pragma unroll
            for (int mi = 0; mi < 4; mi++)
#pragma unroll
                for (int nj = 0; nj < 4; nj++) {
                    const uint32_t* bh = &fBh[nj >> 1][(nj & 1) * 2];
                    const uint32_t* bl = &fBl[nj >> 1][(nj & 1) * 2];
                    mma16816(acc[mi][nj], fAh[mi], bh);
                    mma16816(acc[mi][nj], fAh[mi], bl);
                    mma16816(acc[mi][nj], fAl[mi], bh);
                }
        }
        __syncthreads();
    }

#pragma unroll
    for (int mi = 0; mi < 4; mi++) {
#pragma unroll
        for (int nj = 0; nj < 4; nj++) {
            int n = n0 + warp_n + nj * 8 + (lane & 3) * 2;
            float2 bv = *(const float2*)(bias + n);
            int r0 = m0 + warp_m + mi * 16 + (lane >> 2);
            float o00 = acc[mi][nj][0] + bv.x, o01 = acc[mi][nj][1] + bv.y;
            float o10 = acc[mi][nj][2] + bv.x, o11 = acc[mi][nj][3] + bv.y;
            if (Co) {
                *(float2*)(Co + (size_t)r0 * G_N + n)       = make_float2(o00, o01);
                *(float2*)(Co + (size_t)(r0 + 8) * G_N + n) = make_float2(o10, o11);
            } else {
                uint32_t h0 = pack_bf16x2(o00, o01);
                __nv_bfloat162 h0v = *(__nv_bfloat162*)&h0;
                uint32_t l0 = pack_bf16x2(o00 - __bfloat162float(h0v.x),
                                          o01 - __bfloat162float(h0v.y));
                uint32_t h1 = pack_bf16x2(o10, o11);
                __nv_bfloat162 h1v = *(__nv_bfloat162*)&h1;
                uint32_t l1 = pack_bf16x2(o10 - __bfloat162float(h1v.x),
                                          o11 - __bfloat162float(h1v.y));
                *(uint32_t*)(Ch + (size_t)r0 * G_N + n)       = h0;
                *(uint32_t*)(Cl + (size_t)r0 * G_N + n)       = l0;
                *(uint32_t*)(Ch + (size_t)(r0 + 8) * G_N + n) = h1;
                *(uint32_t*)(Cl + (size_t)(r0 + 8) * G_N + n) = l1;
            }
        }
    }
}

// ---------------- Flash attention (HMMA + cp.async KV pipeline) --------------
// Block: 128 q-rows x (b,h). 8 warps, each 16 q-rows x 64 keys.
// Smem: Q (32KB persistent) + 2 stages x (Kh,Kl,Vh,Vl 8KB each + mask 256B).
#define FKSM 8192
#define FSTG (4 * FKSM + 256)          // 33024 per stage
#define FSM_STG0 32768
#define FLASH_SMEM (32768 + 2 * FSTG)  // 98816

__device__ __forceinline__ void kv_prefetch(
    uint32_t us, const __nv_bfloat16* __restrict__ Kh_,
    const __nv_bfloat16* __restrict__ Kl_, const __nv_bfloat16* __restrict__ Vh_,
    const __nv_bfloat16* __restrict__ Vl_, size_t baseK, int kt,
    const int* __restrict__ maskp, int tid)
{
#pragma unroll
    for (int it = 0; it < 2; it++) {
        int c = tid + it * 256;
        int r = c >> 3, c16 = c & 7;
        uint32_t sw = (uint32_t)(r * 128 + ((c16 ^ (r & 7)) << 4));
        size_t src = baseK + (size_t)(kt * 64 + r) * DMODEL + c16 * 8;
        cp16(us + sw,            Kh_ + src);
        cp16(us + FKSM + sw,     Kl_ + src);
        cp16(us + 2 * FKSM + sw, Vh_ + src);
        cp16(us + 3 * FKSM + sw, Vl_ + src);
    }
    if (tid < 16) cp16(us + 4 * FKSM + tid * 16, maskp + kt * 64 + tid * 4);
}

__global__ __launch_bounds__(256, 1) void flash_hmma(
    const __nv_bfloat16* __restrict__ Qh_, const __nv_bfloat16* __restrict__ Ql_,
    const __nv_bfloat16* __restrict__ Kh_, const __nv_bfloat16* __restrict__ Kl_,
    const __nv_bfloat16* __restrict__ Vh_, const __nv_bfloat16* __restrict__ Vl_,
    const int* __restrict__ mask,
    __nv_bfloat16* __restrict__ Oh_, __nv_bfloat16* __restrict__ Ol_)
{
    extern __shared__ __align__(1024) char smem[];
    const uint32_t u0 = smem_to_u32(smem);
    char* sQh = smem;
    char* sQl = smem + 16384;

    const int tid = threadIdx.x, lane = tid & 31, wid = tid >> 5;
    const int q0 = blockIdx.x * 128;
    const int h  = blockIdx.y;
    const int b  = blockIdx.z;
    const size_t baseQ = ((size_t)b * SEQ + q0) * DMODEL + h * DK;
    const size_t baseK = ((size_t)b * SEQ) * DMODEL + h * DK;
    const int* maskp = mask + b * SEQ;

    // prefetch KV stage 0 first (overlaps with Q staging)
    kv_prefetch(u0 + FSM_STG0, Kh_, Kl_, Vh_, Vl_, baseK, 0, maskp, tid);
    CP_COMMIT();

    // stage Q (regular loads)
#pragma unroll
    for (int it = 0; it < 4; it++) {
        int c = tid + it * 256;
        int r = c >> 3, c16 = c & 7;
        uint32_t sw = (uint32_t)(r * 128 + ((c16 ^ (r & 7)) << 4));
        size_t src = baseQ + (size_t)r * DMODEL + c16 * 8;
        *(uint4*)(sQh + sw) = *(const uint4*)(Qh_ + src);
        *(uint4*)(sQl + sw) = *(const uint4*)(Ql_ + src);
    }
    __syncthreads();

    uint32_t fQh[4][4], fQl[4][4];
    {
        const uint32_t uQh = smem_to_u32(sQh), uQl = smem_to_u32(sQl);
        int r = wid * 16 + (lane & 15);
        int colA = lane >> 4;
#pragma unroll
        for (int ks = 0; ks < 4; ks++) {
            uint32_t off = (uint32_t)(r * 128 + (((ks * 2 + colA) ^ (r & 7)) << 4));
            ldm_x4(fQh[ks], uQh + off);
            ldm_x4(fQl[ks], uQl + off);
        }
    }

    float m0 = -1e30f, m1 = -1e30f, l0 = 0.f, l1 = 0.f;
    float oacc[8][4];
#pragma unroll
    for (int d = 0; d < 8; d++)
#pragma unroll
        for (int f = 0; f < 4; f++) oacc[d][f] = 0.f;

    const int rowB = (lane & 7) + ((lane >> 4) << 3);
    const int colB = (lane >> 3) & 1;
    const int rT = lane & 15;
    const int cT = lane >> 4;

    const int NT = SEQ / 64;  // 32
    for (int kt = 0; kt < NT; kt++) {
        const uint32_t us = u0 + FSM_STG0 + (uint32_t)(kt & 1) * FSTG;
        if (kt + 1 < NT) {
            kv_prefetch(u0 + FSM_STG0 + (uint32_t)((kt + 1) & 1) * FSTG,
                        Kh_, Kl_, Vh_, Vl_, baseK, kt + 1, maskp, tid);
            CP_COMMIT();
            CP_WAIT1();
        } else {
            CP_WAIT0();
        }
        __syncthreads();

        const uint32_t uKh = us, uKl = us + FKSM;
        const uint32_t uVh = us + 2 * FKSM, uVl = us + 3 * FKSM;
        const int* smask = (const int*)(smem + FSM_STG0 + (kt & 1) * FSTG + 4 * FKSM);

        // ---- S = Q K^T ----
        float sacc[8][4];
#pragma unroll
        for (int nj = 0; nj < 8; nj++)
#pragma unroll
            for (int f = 0; f < 4; f++) sacc[nj][f] = 0.f;

#pragma unroll
        for (int ks = 0; ks < 4; ks++) {
            uint32_t fKh[4][4], fKl[4][4];
#pragma unroll
            for (int nj2 = 0; nj2 < 4; nj2++) {
                int r = nj2 * 16 + rowB;
                uint32_t off = (uint32_t)(r * 128 + (((ks * 2 + colB) ^ (r & 7)) << 4));
                ldm_x4(fKh[nj2], uKh + off);
                ldm_x4(fKl[nj2], uKl + off);
            }
#pragma unroll
            for (int nj = 0; nj < 8; nj++) {
                const uint32_t* bh = &fKh[nj >> 1][(nj & 1) * 2];
                const uint32_t* bl = &fKl[nj >> 1][(nj & 1) * 2];
                mma16816(sacc[nj], fQh[ks], bh);
                mma16816(sacc[nj], fQh[ks], bl);
                mma16816(sacc[nj], fQl[ks], bh);
            }
        }

        // ---- online softmax ----
        const float cs = 0.18033688f;  // 0.125 * log2(e)
        float mx0 = -1e30f, mx1 = -1e30f;
#pragma unroll
        for (int nj = 0; nj < 8; nj++) {
            int col = nj * 8 + 2 * (lane & 3);
            bool ma = smask[col] != 0, mb2 = smask[col + 1] != 0;
            float s0 = ma  ? sacc[nj][0] * cs : -1e30f;
            float s1 = mb2 ? sacc[nj][1] * cs : -1e30f;
            float s2 = ma  ? sacc[nj][2] * cs : -1e30f;
            float s3 = mb2 ? sacc[nj][3] * cs : -1e30f;
            sacc[nj][0] = s0; sacc[nj][1] = s1; sacc[nj][2] = s2; sacc[nj][3] = s3;
            mx0 = fmaxf(mx0, fmaxf(s0, s1));
            mx1 = fmaxf(mx1, fmaxf(s2, s3));
        }
        mx0 = fmaxf(mx0, __shfl_xor_sync(0xffffffffu, mx0, 1));
        mx0 = fmaxf(mx0, __shfl_xor_sync(0xffffffffu, mx0, 2));
        mx1 = fmaxf(mx1, __shfl_xor_sync(0xffffffffu, mx1, 1));
        mx1 = fmaxf(mx1, __shfl_xor_sync(0xffffffffu, mx1, 2));

        float mn0 = fmaxf(m0, mx0), mn1 = fmaxf(m1, mx1);
        float cr0 = exp2_fast(m0 - mn0), cr1 = exp2_fast(m1 - mn1);
        m0 = mn0; m1 = mn1;
        l0 *= cr0; l1 *= cr1;
#pragma unroll
        for (int d = 0; d < 8; d++) {
            oacc[d][0] *= cr0; oacc[d][1] *= cr0;
            oacc[d][2] *= cr1; oacc[d][3] *= cr1;
        }

        uint32_t ph01[8], ph23[8], pl01[8], pl23[8];
        float rs0 = 0.f, rs1 = 0.f;
#pragma unroll
        for (int nj = 0; nj < 8; nj++) {
            float p0 = exp2_fast(sacc[nj][0] - mn0);
            float p1 = exp2_fast(sacc[nj][1] - mn0);
            float p2 = exp2_fast(sacc[nj][2] - mn1);
            float p3 = exp2_fast(sacc[nj][3] - mn1);
            rs0 += p0 + p1; rs1 += p2 + p3;
            uint32_t hA = pack_bf16x2(p0, p1);
            uint32_t hB = pack_bf16x2(p2, p3);
            ph01[nj] = hA; ph23[nj] = hB;
            __nv_bfloat162 hA2 = *(__nv_bfloat162*)&hA;
            __nv_bfloat162 hB2 = *(__nv_bfloat162*)&hB;
            pl01[nj] = pack_bf16x2(p0 - __bfloat162float(hA2.x),
                                   p1 - __bfloat162float(hA2.y));
            pl23[nj] = pack_bf16x2(p2 - __bfloat162float(hB2.x),
                                   p3 - __bfloat162float(hB2.y));
        }
        rs0 += __shfl_xor_sync(0xffffffffu, rs0, 1);
        rs0 += __shfl_xor_sync(0xffffffffu, rs0, 2);
        rs1 += __shfl_xor_sync(0xffffffffu, rs1, 1);
        rs1 += __shfl_xor_sync(0xffffffffu, rs1, 2);
        l0 += rs0; l1 += rs1;

        // ---- O += P V ----
#pragma unroll
        for (int kc = 0; kc < 4; kc++) {
            uint32_t aPh[4] = { ph01[2 * kc], ph23[2 * kc], ph01[2 * kc + 1], ph23[2 * kc + 1] };
            uint32_t aPl[4] = { pl01[2 * kc], pl23[2 * kc], pl01[2 * kc + 1], pl23[2 * kc + 1] };
#pragma unroll
            for (int dn = 0; dn < 4; dn++) {
                int r = kc * 16 + rT;
                int c16 = dn * 2 + cT;
                uint32_t off = (uint32_t)(r * 128 + ((c16 ^ (r & 7)) << 4));
                uint32_t tvh[4], tvl[4];
                ldm_x4_t(tvh, uVh + off);
                ldm_x4_t(tvl, uVl + off);
                mma16816(oacc[2 * dn],     aPh, &tvh[0]);
                mma16816(oacc[2 * dn],     aPh, &tvl[0]);
                mma16816(oacc[2 * dn],     aPl, &tvh[0]);
                mma16816(oacc[2 * dn + 1], aPh, &tvh[2]);
                mma16816(oacc[2 * dn + 1], aPh, &tvl[2]);
                mma16816(oacc[2 * dn + 1], aPl, &tvh[2]);
            }
        }
        __syncthreads();
    }

    // ---- epilogue ----
    float inv0 = 1.f / l0, inv1 = 1.f / l1;
    size_t row0 = (size_t)b * SEQ + q0 + wid * 16 + (lane >> 2);
#pragma unroll
    for (int d = 0; d < 8; d++) {
        int col = h * DK + d * 8 + 2 * (lane & 3);
        float o0 = oacc[d][0] * inv0, o1 = oacc[d][1] * inv0;
        uint32_t hh = pack_bf16x2(o0, o1);
        __nv_bfloat162 h2 = *(__nv_bfloat162*)&hh;
        uint32_t ll = pack_bf16x2(o0 - __bfloat162float(h2.x),
                                  o1 - __bfloat162float(h2.y));
        *(uint32_t*)(Oh_ + row0 * DMODEL + col) = hh;
        *(uint32_t*)(Ol_ + row0 * DMODEL + col) = ll;
        float o2 = oacc[d][2] * inv1, o3 = oacc[d][3] * inv1;
        uint32_t hh2 = pack_bf16x2(o2, o3);
        __nv_bfloat162 h3 = *(__nv_bfloat162*)&hh2;
        uint32_t ll2 = pack_bf16x2(o2 - __bfloat162float(h3.x),
                                   o3 - __bfloat162float(h3.y));
        *(uint32_t*)(Oh_ + (row0 + 8) * DMODEL + col) = hh2;
        *(uint32_t*)(Ol_ + (row0 + 8) * DMODEL + col) = ll2;
    }
}

// ---------------- launcher ---------------------------------------------------
extern "C" void kernel_launch(void* const* d_in, const int* in_sizes, int n_in,
                              void* d_out, int out_size)
{
    const float* x    = (const float*)d_in[0];
    const int*   mask = (const int*)  d_in[1];
    const float* Wq = (const float*)d_in[2];
    const float* bq = (const float*)d_in[3];
    const float* Wk = (const float*)d_in[4];
    const float* bk = (const float*)d_in[5];
    const float* Wv = (const float*)d_in[6];
    const float* bv = (const float*)d_in[7];
    const float* Wo = (const float*)d_in[8];
    const float* bo = (const float*)d_in[9];
    float* out = (float*)d_out;

    __nv_bfloat16 *xh, *xl, *wh, *wl, *qh, *ql, *kh, *kl, *vh, *vl;
    cudaGetSymbolAddress((void**)&xh, g_xh);
    cudaGetSymbolAddress((void**)&xl, g_xl);
    cudaGetSymbolAddress((void**)&wh, g_wh);
    cudaGetSymbolAddress((void**)&wl, g_wl);
    cudaGetSymbolAddress((void**)&qh, g_qh);
    cudaGetSymbolAddress((void**)&ql, g_ql);
    cudaGetSymbolAddress((void**)&kh, g_kh);
    cudaGetSymbolAddress((void**)&kl, g_kl);
    cudaGetSymbolAddress((void**)&vh, g_vh);
    cudaGetSymbolAddress((void**)&vl, g_vl);

    cudaFuncSetAttribute(gemm_hmma,
                         cudaFuncAttributeMaxDynamicSharedMemorySize, GEMM_SMEM);
    cudaFuncSetAttribute(flash_hmma,
                         cudaFuncAttributeMaxDynamicSharedMemorySize, FLASH_SMEM);

    const int WSZ = DMODEL * DMODEL;
    const int n4x = MROWS * DMODEL / 4;
    const int n4w = WSZ / 4;

    split_kernel<<<n4x / 256, 256>>>(x, xh, xl, n4x);
    split_kernel<<<n4w / 256, 256>>>(Wq, wh + 0 * WSZ, wl + 0 * WSZ, n4w);
    split_kernel<<<n4w / 256, 256>>>(Wk, wh + 1 * WSZ, wl + 1 * WSZ, n4w);
    split_kernel<<<n4w / 256, 256>>>(Wv, wh + 2 * WSZ, wl + 2 * WSZ, n4w);
    split_kernel<<<n4w / 256, 256>>>(Wo, wh + 3 * WSZ, wl + 3 * WSZ, n4w);

    dim3 ggrid(G_N / 128, MROWS / 128);   // (8, 64)
    gemm_hmma<<<ggrid, 256, GEMM_SMEM>>>(xh, xl, wh + 0 * WSZ, wl + 0 * WSZ, bq,
                                         nullptr, qh, ql);
    gemm_hmma<<<ggrid, 256, GEMM_SMEM>>>(xh, xl, wh + 1 * WSZ, wl + 1 * WSZ, bk,
                                         nullptr, kh, kl);
    gemm_hmma<<<ggrid, 256, GEMM_SMEM>>>(xh, xl, wh + 2 * WSZ, wl + 2 * WSZ, bv,
                                         nullptr, vh, vl);

    dim3 fgrid(SEQ / 128, NHEADS, BATCH); // (16, 16, 4)
    flash_hmma<<<fgrid, 256, FLASH_SMEM>>>(qh, ql, kh, kl, vh, vl, mask, xh, xl);

    gemm_hmma<<<ggrid, 256, GEMM_SMEM>>>(xh, xl, wh + 3 * WSZ, wl + 3 * WSZ, bo,
                                         out, nullptr, nullptr);
}

// round 6
// speedup vs baseline: 4.9544x; 1.4157x over previous
#include <cuda_runtime.h>
#include <cuda_fp16.h>
#include <math.h>
#include <cstdint>

// Problem constants
#define BATCH 4
#define SEQ   2048
#define DMODEL 1024
#define NHEADS 16
#define DK    64
#define MROWS (BATCH * SEQ)   // 8192
#define G_K 1024
#define G_N 1024

// ---------------- scratch (static device globals; no runtime allocation) ----
__device__ __half g_xh[MROWS * DMODEL];
__device__ __half g_xl[MROWS * DMODEL];
__device__ __half g_w[4][DMODEL * DMODEL];
__device__ __half g_qh[MROWS * DMODEL];
__device__ __half g_ql[MROWS * DMODEL];
__device__ __half g_k[MROWS * DMODEL];
__device__ __half g_v[MROWS * DMODEL];

// ---------------- helpers ----------------------------------------------------
__device__ __forceinline__ uint32_t smem_to_u32(const void* p) {
    uint32_t a;
    asm("{ .reg .u64 t; cvta.to.shared.u64 t, %1; cvt.u32.u64 %0, t; }" : "=r"(a) : "l"(p));
    return a;
}
__device__ __forceinline__ void cp16(uint32_t s, const void* g) {
    asm volatile("cp.async.cg.shared.global [%0], [%1], 16;" :: "r"(s), "l"(g));
}
#define CP_COMMIT() asm volatile("cp.async.commit_group;" ::: "memory")
#define CP_WAIT1()  asm volatile("cp.async.wait_group 1;" ::: "memory")
#define CP_WAIT0()  asm volatile("cp.async.wait_group 0;" ::: "memory")

__device__ __forceinline__ void ldm_x4(uint32_t* r, uint32_t addr) {
    asm volatile("ldmatrix.sync.aligned.m8n8.x4.shared.b16 {%0,%1,%2,%3}, [%4];"
                 : "=r"(r[0]), "=r"(r[1]), "=r"(r[2]), "=r"(r[3]) : "r"(addr));
}
__device__ __forceinline__ void ldm_x4_t(uint32_t* r, uint32_t addr) {
    asm volatile("ldmatrix.sync.aligned.m8n8.x4.trans.shared.b16 {%0,%1,%2,%3}, [%4];"
                 : "=r"(r[0]), "=r"(r[1]), "=r"(r[2]), "=r"(r[3]) : "r"(addr));
}
__device__ __forceinline__ void mma16816(float* c, const uint32_t* a, const uint32_t* b) {
    asm volatile("mma.sync.aligned.m16n8k16.row.col.f32.f16.f16.f32 "
                 "{%0,%1,%2,%3}, {%4,%5,%6,%7}, {%8,%9}, {%0,%1,%2,%3};"
                 : "+f"(c[0]), "+f"(c[1]), "+f"(c[2]), "+f"(c[3])
                 : "r"(a[0]), "r"(a[1]), "r"(a[2]), "r"(a[3]), "r"(b[0]), "r"(b[1]));
}
__device__ __forceinline__ uint32_t pack_h2(float lo, float hi) {
    __half2 h = __floats2half2_rn(lo, hi);
    return *(uint32_t*)&h;
}
// fast 2^x on the FMA pipe (no MUFU). rel err ~2e-6.
__device__ __forceinline__ float exp2_fast(float x) {
    x = fmaxf(x, -100.f);
    float t = x + 12582912.f;
    int   n = __float_as_int(t) - 0x4B400000;
    float f = x - (t - 12582912.f);
    float p = 0.0013333558f;
    p = fmaf(p, f, 0.0096181291f);
    p = fmaf(p, f, 0.0555041087f);
    p = fmaf(p, f, 0.2402265069f);
    p = fmaf(p, f, 0.6931471806f);
    p = fmaf(p, f, 1.0f);
    return __int_as_float(__float_as_int(p) + (n << 23));
}

// ---------------- split fp32 -> fp16 hi + fp16 lo ----------------------------
__global__ __launch_bounds__(256) void split_kernel(
    const float* __restrict__ in, __half* __restrict__ hi,
    __half* __restrict__ lo, int n4)
{
    int i = blockIdx.x * blockDim.x + threadIdx.x;
    if (i >= n4) return;
    float4 x = ((const float4*)in)[i];
    __half h0 = __float2half(x.x), h1 = __float2half(x.y);
    __half h2 = __float2half(x.z), h3 = __float2half(x.w);
    ((__half2*)hi)[2 * i + 0] = __half2(h0, h1);
    ((__half2*)hi)[2 * i + 1] = __half2(h2, h3);
    ((__half2*)lo)[2 * i + 0] = __half2(__float2half(x.x - __half2float(h0)),
                                        __float2half(x.y - __half2float(h1)));
    ((__half2*)lo)[2 * i + 1] = __half2(__float2half(x.z - __half2float(h2)),
                                        __float2half(x.w - __half2float(h3)));
}

// ---------------- convert fp32 -> fp16 (weights) ------------------------------
__global__ __launch_bounds__(256) void convert_kernel(
    const float* __restrict__ in, __half* __restrict__ out, int n4)
{
    int i = blockIdx.x * blockDim.x + threadIdx.x;
    if (i >= n4) return;
    float4 x = ((const float4*)in)[i];
    ((__half2*)out)[2 * i + 0] = __floats2half2_rn(x.x, x.y);
    ((__half2*)out)[2 * i + 1] = __floats2half2_rn(x.z, x.w);
}

// ---------------- HMMA GEMM, 2-stage cp.async, 2-term fp16 -------------------
// C = (Ah+Al) @ B^T + bias.  128x128 tile, K-chunk 64, 8 warps (2m x 4n).
#define GSM 16384
#define GSTG (3 * GSM)          // 48KB per stage: Ah, Al, B
#define GEMM_SMEM (2 * GSTG)    // 96KB

__device__ __forceinline__ void gemm_prefetch(
    uint32_t us, const __half* __restrict__ Ah, const __half* __restrict__ Al,
    const __half* __restrict__ B, int m0, int n0, int k0, int tid)
{
#pragma unroll
    for (int it = 0; it < 4; it++) {
        int c = tid + it * 256;
        int r = c >> 3, c16 = c & 7;
        uint32_t sw = (uint32_t)(r * 128 + ((c16 ^ (r & 7)) << 4));
        size_t aoff = (size_t)(m0 + r) * G_K + k0 + c16 * 8;
        size_t boff = (size_t)(n0 + r) * G_K + k0 + c16 * 8;
        cp16(us + sw,           Ah + aoff);
        cp16(us + GSM + sw,     Al + aoff);
        cp16(us + 2 * GSM + sw, B + boff);
    }
}

__global__ __launch_bounds__(256, 1) void gemm_hmma(
    const __half* __restrict__ Ah, const __half* __restrict__ Al,
    const __half* __restrict__ B, const float* __restrict__ bias,
    float* __restrict__ Co, __half* __restrict__ Ch, __half* __restrict__ Cl)
{
    extern __shared__ __align__(1024) char smem[];
    const uint32_t u0 = smem_to_u32(smem);

    const int tid  = threadIdx.x;
    const int lane = tid & 31;
    const int wid  = tid >> 5;
    const int m0 = blockIdx.y * 128;
    const int n0 = blockIdx.x * 128;
    const int warp_m = (wid & 1) * 64;
    const int warp_n = (wid >> 1) * 32;

    float acc[4][4][4];
#pragma unroll
    for (int i = 0; i < 4; i++)
#pragma unroll
        for (int j = 0; j < 4; j++)
#pragma unroll
            for (int f = 0; f < 4; f++) acc[i][j][f] = 0.f;

    const int rowA = (lane & 15);
    const int colA = (lane >> 4);
    const int rowB = (lane & 7) + ((lane >> 4) << 3);
    const int colB = ((lane >> 3) & 1);

    gemm_prefetch(u0, Ah, Al, B, m0, n0, 0, tid);
    CP_COMMIT();

    const int NT = G_K / 64;  // 16
    for (int kt = 0; kt < NT; kt++) {
        const uint32_t us = u0 + (uint32_t)(kt & 1) * GSTG;
        if (kt + 1 < NT) {
            gemm_prefetch(u0 + (uint32_t)((kt + 1) & 1) * GSTG,
                          Ah, Al, B, m0, n0, (kt + 1) * 64, tid);
            CP_COMMIT();
            CP_WAIT1();
        } else {
            CP_WAIT0();
        }
        __syncthreads();

        const uint32_t uAh = us, uAl = us + GSM, uB = us + 2 * GSM;
#pragma unroll
        for (int ks = 0; ks < 4; ks++) {
            uint32_t fAh[4][4], fAl[4][4], fB[2][4];
#pragma unroll
            for (int mi = 0; mi < 4; mi++) {
                int r = warp_m + mi * 16 + rowA;
                uint32_t off = (uint32_t)(r * 128 + (((ks * 2 + colA) ^ (r & 7)) << 4));
                ldm_x4(fAh[mi], uAh + off);
                ldm_x4(fAl[mi], uAl + off);
            }
#pragma unroll
            for (int nj2 = 0; nj2 < 2; nj2++) {
                int r = warp_n + nj2 * 16 + rowB;
                uint32_t off = (uint32_t)(r * 128 + (((ks * 2 + colB) ^ (r & 7)) << 4));
                ldm_x4(fB[nj2], uB + off);
            }
#pragma unroll
            for (int mi = 0; mi < 4; mi++)
#pragma unroll
                for (int nj = 0; nj < 4; nj++) {
                    const uint32_t* bb = &fB[nj >> 1][(nj & 1) * 2];
                    mma16816(acc[mi][nj], fAh[mi], bb);
                    mma16816(acc[mi][nj], fAl[mi], bb);
                }
        }
        __syncthreads();
    }

#pragma unroll
    for (int mi = 0; mi < 4; mi++) {
#pragma unroll
        for (int nj = 0; nj < 4; nj++) {
            int n = n0 + warp_n + nj * 8 + (lane & 3) * 2;
            float2 bv = *(const float2*)(bias + n);
            int r0 = m0 + warp_m + mi * 16 + (lane >> 2);
            float o00 = acc[mi][nj][0] + bv.x, o01 = acc[mi][nj][1] + bv.y;
            float o10 = acc[mi][nj][2] + bv.x, o11 = acc[mi][nj][3] + bv.y;
            if (Co) {
                *(float2*)(Co + (size_t)r0 * G_N + n)       = make_float2(o00, o01);
                *(float2*)(Co + (size_t)(r0 + 8) * G_N + n) = make_float2(o10, o11);
            } else if (Cl) {
                // hi/lo split output
                uint32_t h0 = pack_h2(o00, o01);
                __half2 h0v = *(__half2*)&h0;
                uint32_t l0 = pack_h2(o00 - __half2float(h0v.x),
                                      o01 - __half2float(h0v.y));
                uint32_t h1 = pack_h2(o10, o11);
                __half2 h1v = *(__half2*)&h1;
                uint32_t l1 = pack_h2(o10 - __half2float(h1v.x),
                                      o11 - __half2float(h1v.y));
                *(uint32_t*)(Ch + (size_t)r0 * G_N + n)       = h0;
                *(uint32_t*)(Cl + (size_t)r0 * G_N + n)       = l0;
                *(uint32_t*)(Ch + (size_t)(r0 + 8) * G_N + n) = h1;
                *(uint32_t*)(Cl + (size_t)(r0 + 8) * G_N + n) = l1;
            } else {
                // single fp16 output
                *(uint32_t*)(Ch + (size_t)r0 * G_N + n)       = pack_h2(o00, o01);
                *(uint32_t*)(Ch + (size_t)(r0 + 8) * G_N + n) = pack_h2(o10, o11);
            }
        }
    }
}

// ---------------- Flash attention (fp16 HMMA + cp.async KV pipeline) ---------
// S = (Qh+Ql) K^T (2-term), O += P V (1-term, P,V single fp16).
#define FKSM 8192
#define FSTG (2 * FKSM + 256)          // 16640 per stage: K, V, mask
#define FSM_STG0 32768
#define FLASH_SMEM (32768 + 2 * FSTG)  // 66048

__device__ __forceinline__ void kv_prefetch(
    uint32_t us, const __half* __restrict__ K_, const __half* __restrict__ V_,
    size_t baseK, int kt, const int* __restrict__ maskp, int tid)
{
#pragma unroll
    for (int it = 0; it < 2; it++) {
        int c = tid + it * 256;
        int r = c >> 3, c16 = c & 7;
        uint32_t sw = (uint32_t)(r * 128 + ((c16 ^ (r & 7)) << 4));
        size_t src = baseK + (size_t)(kt * 64 + r) * DMODEL + c16 * 8;
        cp16(us + sw,        K_ + src);
        cp16(us + FKSM + sw, V_ + src);
    }
    if (tid < 16) cp16(us + 2 * FKSM + tid * 16, maskp + kt * 64 + tid * 4);
}

__global__ __launch_bounds__(256, 1) void flash_hmma(
    const __half* __restrict__ Qh_, const __half* __restrict__ Ql_,
    const __half* __restrict__ K_, const __half* __restrict__ V_,
    const int* __restrict__ mask,
    __half* __restrict__ Oh_, __half* __restrict__ Ol_)
{
    extern __shared__ __align__(1024) char smem[];
    const uint32_t u0 = smem_to_u32(smem);
    char* sQh = smem;
    char* sQl = smem + 16384;

    const int tid = threadIdx.x, lane = tid & 31, wid = tid >> 5;
    const int q0 = blockIdx.x * 128;
    const int h  = blockIdx.y;
    const int b  = blockIdx.z;
    const size_t baseQ = ((size_t)b * SEQ + q0) * DMODEL + h * DK;
    const size_t baseK = ((size_t)b * SEQ) * DMODEL + h * DK;
    const int* maskp = mask + b * SEQ;

    kv_prefetch(u0 + FSM_STG0, K_, V_, baseK, 0, maskp, tid);
    CP_COMMIT();

    // stage Q (regular loads)
#pragma unroll
    for (int it = 0; it < 4; it++) {
        int c = tid + it * 256;
        int r = c >> 3, c16 = c & 7;
        uint32_t sw = (uint32_t)(r * 128 + ((c16 ^ (r & 7)) << 4));
        size_t src = baseQ + (size_t)r * DMODEL + c16 * 8;
        *(uint4*)(sQh + sw) = *(const uint4*)(Qh_ + src);
        *(uint4*)(sQl + sw) = *(const uint4*)(Ql_ + src);
    }
    __syncthreads();

    uint32_t fQh[4][4], fQl[4][4];
    {
        const uint32_t uQh = smem_to_u32(sQh), uQl = smem_to_u32(sQl);
        int r = wid * 16 + (lane & 15);
        int colA = lane >> 4;
#pragma unroll
        for (int ks = 0; ks < 4; ks++) {
            uint32_t off = (uint32_t)(r * 128 + (((ks * 2 + colA) ^ (r & 7)) << 4));
            ldm_x4(fQh[ks], uQh + off);
            ldm_x4(fQl[ks], uQl + off);
        }
    }

    float m0 = -1e30f, m1 = -1e30f, l0 = 0.f, l1 = 0.f;
    float oacc[8][4];
#pragma unroll
    for (int d = 0; d < 8; d++)
#pragma unroll
        for (int f = 0; f < 4; f++) oacc[d][f] = 0.f;

    const int rowB = (lane & 7) + ((lane >> 4) << 3);
    const int colB = (lane >> 3) & 1;
    const int rT = lane & 15;
    const int cT = lane >> 4;

    const int NT = SEQ / 64;  // 32
    for (int kt = 0; kt < NT; kt++) {
        const uint32_t us = u0 + FSM_STG0 + (uint32_t)(kt & 1) * FSTG;
        if (kt + 1 < NT) {
            kv_prefetch(u0 + FSM_STG0 + (uint32_t)((kt + 1) & 1) * FSTG,
                        K_, V_, baseK, kt + 1, maskp, tid);
            CP_COMMIT();
            CP_WAIT1();
        } else {
            CP_WAIT0();
        }
        __syncthreads();

        const uint32_t uK = us, uV = us + FKSM;
        const int* smask = (const int*)(smem + FSM_STG0 + (kt & 1) * FSTG + 2 * FKSM);

        // ---- S = Q K^T (2-term) ----
        float sacc[8][4];
#pragma unroll
        for (int nj = 0; nj < 8; nj++)
#pragma unroll
            for (int f = 0; f < 4; f++) sacc[nj][f] = 0.f;

#pragma unroll
        for (int ks = 0; ks < 4; ks++) {
            uint32_t fK[4][4];
#pragma unroll
            for (int nj2 = 0; nj2 < 4; nj2++) {
                int r = nj2 * 16 + rowB;
                uint32_t off = (uint32_t)(r * 128 + (((ks * 2 + colB) ^ (r & 7)) << 4));
                ldm_x4(fK[nj2], uK + off);
            }
#pragma unroll
            for (int nj = 0; nj < 8; nj++) {
                const uint32_t* bb = &fK[nj >> 1][(nj & 1) * 2];
                mma16816(sacc[nj], fQh[ks], bb);
                mma16816(sacc[nj], fQl[ks], bb);
            }
        }

        // ---- online softmax (exp2 on FMA pipe) ----
        const float cs = 0.18033688f;  // 0.125 * log2(e)
        float mx0 = -1e30f, mx1 = -1e30f;
#pragma unroll
        for (int nj = 0; nj < 8; nj++) {
            int col = nj * 8 + 2 * (lane & 3);
            bool ma = smask[col] != 0, mb2 = smask[col + 1] != 0;
            float s0 = ma  ? sacc[nj][0] * cs : -1e30f;
            float s1 = mb2 ? sacc[nj][1] * cs : -1e30f;
            float s2 = ma  ? sacc[nj][2] * cs : -1e30f;
            float s3 = mb2 ? sacc[nj][3] * cs : -1e30f;
            sacc[nj][0] = s0; sacc[nj][1] = s1; sacc[nj][2] = s2; sacc[nj][3] = s3;
            mx0 = fmaxf(mx0, fmaxf(s0, s1));
            mx1 = fmaxf(mx1, fmaxf(s2, s3));
        }
        mx0 = fmaxf(mx0, __shfl_xor_sync(0xffffffffu, mx0, 1));
        mx0 = fmaxf(mx0, __shfl_xor_sync(0xffffffffu, mx0, 2));
        mx1 = fmaxf(mx1, __shfl_xor_sync(0xffffffffu, mx1, 1));
        mx1 = fmaxf(mx1, __shfl_xor_sync(0xffffffffu, mx1, 2));

        float mn0 = fmaxf(m0, mx0), mn1 = fmaxf(m1, mx1);
        float cr0 = exp2_fast(m0 - mn0), cr1 = exp2_fast(m1 - mn1);
        m0 = mn0; m1 = mn1;
        l0 *= cr0; l1 *= cr1;
#pragma unroll
        for (int d = 0; d < 8; d++) {
            oacc[d][0] *= cr0; oacc[d][1] *= cr0;
            oacc[d][2] *= cr1; oacc[d][3] *= cr1;
        }

        uint32_t ph01[8], ph23[8];
        float rs0 = 0.f, rs1 = 0.f;
#pragma unroll
        for (int nj = 0; nj < 8; nj++) {
            float p0 = exp2_fast(sacc[nj][0] - mn0);
            float p1 = exp2_fast(sacc[nj][1] - mn0);
            float p2 = exp2_fast(sacc[nj][2] - mn1);
            float p3 = exp2_fast(sacc[nj][3] - mn1);
            rs0 += p0 + p1; rs1 += p2 + p3;
            ph01[nj] = pack_h2(p0, p1);
            ph23[nj] = pack_h2(p2, p3);
        }
        rs0 += __shfl_xor_sync(0xffffffffu, rs0, 1);
        rs0 += __shfl_xor_sync(0xffffffffu, rs0, 2);
        rs1 += __shfl_xor_sync(0xffffffffu, rs1, 1);
        rs1 += __shfl_xor_sync(0xffffffffu, rs1, 2);
        l0 += rs0; l1 += rs1;

        // ---- O += P V (1-term) ----
#pragma unroll
        for (int kc = 0; kc < 4; kc++) {
            uint32_t aP[4] = { ph01[2 * kc], ph23[2 * kc], ph01[2 * kc + 1], ph23[2 * kc + 1] };
#pragma unroll
            for (int dn = 0; dn < 4; dn++) {
                int r = kc * 16 + rT;
                int c16 = dn * 2 + cT;
                uint32_t off = (uint32_t)(r * 128 + ((c16 ^ (r & 7)) << 4));
                uint32_t tv[4];
                ldm_x4_t(tv, uV + off);
                mma16816(oacc[2 * dn],     aP, &tv[0]);
                mma16816(oacc[2 * dn + 1], aP, &tv[2]);
            }
        }
        __syncthreads();
    }

    // ---- epilogue: normalize, split hi/lo, store ----
    float inv0 = 1.f / l0, inv1 = 1.f / l1;
    size_t row0 = (size_t)b * SEQ + q0 + wid * 16 + (lane >> 2);
#pragma unroll
    for (int d = 0; d < 8; d++) {
        int col = h * DK + d * 8 + 2 * (lane & 3);
        float o0 = oacc[d][0] * inv0, o1 = oacc[d][1] * inv0;
        uint32_t hh = pack_h2(o0, o1);
        __half2 h2 = *(__half2*)&hh;
        uint32_t ll = pack_h2(o0 - __half2float(h2.x), o1 - __half2float(h2.y));
        *(uint32_t*)(Oh_ + row0 * DMODEL + col) = hh;
        *(uint32_t*)(Ol_ + row0 * DMODEL + col) = ll;
        float o2 = oacc[d][2] * inv1, o3 = oacc[d][3] * inv1;
        uint32_t hh2 = pack_h2(o2, o3);
        __half2 h3 = *(__half2*)&hh2;
        uint32_t ll2 = pack_h2(o2 - __half2float(h3.x), o3 - __half2float(h3.y));
        *(uint32_t*)(Oh_ + (row0 + 8) * DMODEL + col) = hh2;
        *(uint32_t*)(Ol_ + (row0 + 8) * DMODEL + col) = ll2;
    }
}

// ---------------- launcher ---------------------------------------------------
extern "C" void kernel_launch(void* const* d_in, const int* in_sizes, int n_in,
                              void* d_out, int out_size)
{
    const float* x    = (const float*)d_in[0];
    const int*   mask = (const int*)  d_in[1];
    const float* Wq = (const float*)d_in[2];
    const float* bq = (const float*)d_in[3];
    const float* Wk = (const float*)d_in[4];
    const float* bk = (const float*)d_in[5];
    const float* Wv = (const float*)d_in[6];
    const float* bv = (const float*)d_in[7];
    const float* Wo = (const float*)d_in[8];
    const float* bo = (const float*)d_in[9];
    float* out = (float*)d_out;

    __half *xh, *xl, *w, *qh, *ql, *k, *v;
    cudaGetSymbolAddress((void**)&xh, g_xh);
    cudaGetSymbolAddress((void**)&xl, g_xl);
    cudaGetSymbolAddress((void**)&w,  g_w);
    cudaGetSymbolAddress((void**)&qh, g_qh);
    cudaGetSymbolAddress((void**)&ql, g_ql);
    cudaGetSymbolAddress((void**)&k,  g_k);
    cudaGetSymbolAddress((void**)&v,  g_v);

    cudaFuncSetAttribute(gemm_hmma,
                         cudaFuncAttributeMaxDynamicSharedMemorySize, GEMM_SMEM);
    cudaFuncSetAttribute(flash_hmma,
                         cudaFuncAttributeMaxDynamicSharedMemorySize, FLASH_SMEM);

    const int WSZ = DMODEL * DMODEL;
    const int n4x = MROWS * DMODEL / 4;
    const int n4w = WSZ / 4;

    split_kernel<<<n4x / 256, 256>>>(x, xh, xl, n4x);
    convert_kernel<<<n4w / 256, 256>>>(Wq, w + 0 * WSZ, n4w);
    convert_kernel<<<n4w / 256, 256>>>(Wk, w + 1 * WSZ, n4w);
    convert_kernel<<<n4w / 256, 256>>>(Wv, w + 2 * WSZ, n4w);
    convert_kernel<<<n4w / 256, 256>>>(Wo, w + 3 * WSZ, n4w);

    dim3 ggrid(G_N / 128, MROWS / 128);   // (8, 64)
    gemm_hmma<<<ggrid, 256, GEMM_SMEM>>>(xh, xl, w + 0 * WSZ, bq, nullptr, qh, ql);
    gemm_hmma<<<ggrid, 256, GEMM_SMEM>>>(xh, xl, w + 1 * WSZ, bk, nullptr, k, nullptr);
    gemm_hmma<<<ggrid, 256, GEMM_SMEM>>>(xh, xl, w + 2 * WSZ, bv, nullptr, v, nullptr);

    dim3 fgrid(SEQ / 128, NHEADS, BATCH); // (16, 16, 4)
    flash_hmma<<<fgrid, 256, FLASH_SMEM>>>(qh, ql, k, v, mask, xh, xl);

    gemm_hmma<<<ggrid, 256, GEMM_SMEM>>>(xh, xl, w + 3 * WSZ, bo, out, nullptr, nullptr);
}

// round 7
// speedup vs baseline: 5.7471x; 1.1600x over previous
#include <cuda_runtime.h>
#include <cuda_fp16.h>
#include <math.h>
#include <cstdint>

// Problem constants
#define BATCH 4
#define SEQ   2048
#define DMODEL 1024
#define NHEADS 16
#define DK    64
#define MROWS (BATCH * SEQ)   // 8192
#define G_K 1024
#define G_N 1024

// ---------------- scratch (static device globals; no runtime allocation) ----
__device__ __half g_xh[MROWS * DMODEL];
__device__ __half g_xl[MROWS * DMODEL];
__device__ __half g_w[4][DMODEL * DMODEL];
__device__ __half g_qh[MROWS * DMODEL];
__device__ __half g_ql[MROWS * DMODEL];
__device__ __half g_k[MROWS * DMODEL];
__device__ __half g_v[MROWS * DMODEL];

// ---------------- helpers ----------------------------------------------------
__device__ __forceinline__ uint32_t smem_to_u32(const void* p) {
    uint32_t a;
    asm("{ .reg .u64 t; cvta.to.shared.u64 t, %1; cvt.u32.u64 %0, t; }" : "=r"(a) : "l"(p));
    return a;
}
__device__ __forceinline__ void cp16(uint32_t s, const void* g) {
    asm volatile("cp.async.cg.shared.global [%0], [%1], 16;" :: "r"(s), "l"(g));
}
#define CP_COMMIT() asm volatile("cp.async.commit_group;" ::: "memory")
#define CP_WAIT2()  asm volatile("cp.async.wait_group 2;" ::: "memory")
#define CP_WAIT1()  asm volatile("cp.async.wait_group 1;" ::: "memory")
#define CP_WAIT0()  asm volatile("cp.async.wait_group 0;" ::: "memory")

__device__ __forceinline__ void ldm_x4(uint32_t* r, uint32_t addr) {
    asm volatile("ldmatrix.sync.aligned.m8n8.x4.shared.b16 {%0,%1,%2,%3}, [%4];"
                 : "=r"(r[0]), "=r"(r[1]), "=r"(r[2]), "=r"(r[3]) : "r"(addr));
}
__device__ __forceinline__ void ldm_x4_t(uint32_t* r, uint32_t addr) {
    asm volatile("ldmatrix.sync.aligned.m8n8.x4.trans.shared.b16 {%0,%1,%2,%3}, [%4];"
                 : "=r"(r[0]), "=r"(r[1]), "=r"(r[2]), "=r"(r[3]) : "r"(addr));
}
__device__ __forceinline__ void mma16816(float* c, const uint32_t* a, const uint32_t* b) {
    asm volatile("mma.sync.aligned.m16n8k16.row.col.f32.f16.f16.f32 "
                 "{%0,%1,%2,%3}, {%4,%5,%6,%7}, {%8,%9}, {%0,%1,%2,%3};"
                 : "+f"(c[0]), "+f"(c[1]), "+f"(c[2]), "+f"(c[3])
                 : "r"(a[0]), "r"(a[1]), "r"(a[2]), "r"(a[3]), "r"(b[0]), "r"(b[1]));
}
__device__ __forceinline__ uint32_t pack_h2(float lo, float hi) {
    __half2 h = __floats2half2_rn(lo, hi);
    return *(uint32_t*)&h;
}
// fast 2^x on the FMA pipe (no MUFU). rel err ~2e-6.
__device__ __forceinline__ float exp2_fast(float x) {
    x = fmaxf(x, -100.f);
    float t = x + 12582912.f;
    int   n = __float_as_int(t) - 0x4B400000;
    float f = x - (t - 12582912.f);
    float p = 0.0013333558f;
    p = fmaf(p, f, 0.0096181291f);
    p = fmaf(p, f, 0.0555041087f);
    p = fmaf(p, f, 0.2402265069f);
    p = fmaf(p, f, 0.6931471806f);
    p = fmaf(p, f, 1.0f);
    return __int_as_float(__float_as_int(p) + (n << 23));
}

// ---------------- convert fp32 -> fp16 ----------------------------------------
__global__ __launch_bounds__(256) void convert_kernel(
    const float* __restrict__ in, __half* __restrict__ out, int n4)
{
    int i = blockIdx.x * blockDim.x + threadIdx.x;
    if (i >= n4) return;
    float4 x = ((const float4*)in)[i];
    ((__half2*)out)[2 * i + 0] = __floats2half2_rn(x.x, x.y);
    ((__half2*)out)[2 * i + 1] = __floats2half2_rn(x.z, x.w);
}

// 4 weight matrices in one launch
__global__ __launch_bounds__(256) void convert_w4(
    const float* __restrict__ w0, const float* __restrict__ w1,
    const float* __restrict__ w2, const float* __restrict__ w3,
    __half* __restrict__ out, int n4each)
{
    int i = blockIdx.x * blockDim.x + threadIdx.x;
    int seg = i / n4each, j = i - seg * n4each;
    if (seg >= 4) return;
    const float* src = (seg == 0) ? w0 : (seg == 1) ? w1 : (seg == 2) ? w2 : w3;
    float4 x = ((const float4*)src)[j];
    __half2* dst = (__half2*)(out + (size_t)seg * n4each * 4);
    dst[2 * j + 0] = __floats2half2_rn(x.x, x.y);
    dst[2 * j + 1] = __floats2half2_rn(x.z, x.w);
}

// ---------------- HMMA GEMM, 3-stage cp.async, TERMS in {1,2} ----------------
// C = (Ah [+ Al]) @ B^T + bias.  128x128 tile, K-chunk 64, 8 warps (2m x 4n).
#define GSM 16384

template <int TERMS>
__device__ __forceinline__ void gemm_prefetch(
    uint32_t us, const __half* __restrict__ Ah, const __half* __restrict__ Al,
    const __half* __restrict__ B, int m0, int n0, int k0, int tid)
{
#pragma unroll
    for (int it = 0; it < 4; it++) {
        int c = tid + it * 256;
        int r = c >> 3, c16 = c & 7;
        uint32_t sw = (uint32_t)(r * 128 + ((c16 ^ (r & 7)) << 4));
        size_t aoff = (size_t)(m0 + r) * G_K + k0 + c16 * 8;
        size_t boff = (size_t)(n0 + r) * G_K + k0 + c16 * 8;
        cp16(us + sw, Ah + aoff);
        if (TERMS == 2) cp16(us + GSM + sw, Al + aoff);
        cp16(us + (TERMS == 2 ? 2 : 1) * GSM + sw, B + boff);
    }
}

template <int TERMS>
__global__ __launch_bounds__(256, 1) void gemm_hmma(
    const __half* __restrict__ Ah, const __half* __restrict__ Al,
    const __half* __restrict__ B, const float* __restrict__ bias,
    float* __restrict__ Co, __half* __restrict__ Ch, __half* __restrict__ Cl)
{
    extern __shared__ __align__(1024) char smem[];
    const uint32_t u0 = smem_to_u32(smem);
    const uint32_t GSTG = (TERMS == 2 ? 3 : 2) * GSM;

    const int tid  = threadIdx.x;
    const int lane = tid & 31;
    const int wid  = tid >> 5;
    const int m0 = blockIdx.y * 128;
    const int n0 = blockIdx.x * 128;
    const int warp_m = (wid & 1) * 64;
    const int warp_n = (wid >> 1) * 32;

    float acc[4][4][4];
#pragma unroll
    for (int i = 0; i < 4; i++)
#pragma unroll
        for (int j = 0; j < 4; j++)
#pragma unroll
            for (int f = 0; f < 4; f++) acc[i][j][f] = 0.f;

    const int rowA = (lane & 15);
    const int colA = (lane >> 4);
    const int rowB = (lane & 7) + ((lane >> 4) << 3);
    const int colB = ((lane >> 3) & 1);

    gemm_prefetch<TERMS>(u0,        Ah, Al, B, m0, n0, 0,  tid); CP_COMMIT();
    gemm_prefetch<TERMS>(u0 + GSTG, Ah, Al, B, m0, n0, 64, tid); CP_COMMIT();

    const int NT = G_K / 64;  // 16
    for (int kt = 0; kt < NT; kt++) {
        if (kt + 2 < NT) {
            gemm_prefetch<TERMS>(u0 + (uint32_t)((kt + 2) % 3) * GSTG,
                                 Ah, Al, B, m0, n0, (kt + 2) * 64, tid);
            CP_COMMIT();
            CP_WAIT2();
        } else if (kt + 1 < NT) {
            CP_WAIT1();
        } else {
            CP_WAIT0();
        }
        __syncthreads();

        const uint32_t us = u0 + (uint32_t)(kt % 3) * GSTG;
        const uint32_t uAh = us, uAl = us + GSM;
        const uint32_t uB  = us + (TERMS == 2 ? 2 : 1) * GSM;
#pragma unroll
        for (int ks = 0; ks < 4; ks++) {
            uint32_t fAh[4][4], fAl[4][4], fB[2][4];
#pragma unroll
            for (int mi = 0; mi < 4; mi++) {
                int r = warp_m + mi * 16 + rowA;
                uint32_t off = (uint32_t)(r * 128 + (((ks * 2 + colA) ^ (r & 7)) << 4));
                ldm_x4(fAh[mi], uAh + off);
                if (TERMS == 2) ldm_x4(fAl[mi], uAl + off);
            }
#pragma unroll
            for (int nj2 = 0; nj2 < 2; nj2++) {
                int r = warp_n + nj2 * 16 + rowB;
                uint32_t off = (uint32_t)(r * 128 + (((ks * 2 + colB) ^ (r & 7)) << 4));
                ldm_x4(fB[nj2], uB + off);
            }
#pragma unroll
            for (int mi = 0; mi < 4; mi++)
#pragma unroll
                for (int nj = 0; nj < 4; nj++) {
                    const uint32_t* bb = &fB[nj >> 1][(nj & 1) * 2];
                    mma16816(acc[mi][nj], fAh[mi], bb);
                    if (TERMS == 2) mma16816(acc[mi][nj], fAl[mi], bb);
                }
        }
        __syncthreads();
    }

#pragma unroll
    for (int mi = 0; mi < 4; mi++) {
#pragma unroll
        for (int nj = 0; nj < 4; nj++) {
            int n = n0 + warp_n + nj * 8 + (lane & 3) * 2;
            float2 bv = *(const float2*)(bias + n);
            int r0 = m0 + warp_m + mi * 16 + (lane >> 2);
            float o00 = acc[mi][nj][0] + bv.x, o01 = acc[mi][nj][1] + bv.y;
            float o10 = acc[mi][nj][2] + bv.x, o11 = acc[mi][nj][3] + bv.y;
            if (Co) {
                *(float2*)(Co + (size_t)r0 * G_N + n)       = make_float2(o00, o01);
                *(float2*)(Co + (size_t)(r0 + 8) * G_N + n) = make_float2(o10, o11);
            } else if (Cl) {
                uint32_t h0 = pack_h2(o00, o01);
                __half2 h0v = *(__half2*)&h0;
                uint32_t l0 = pack_h2(o00 - __half2float(h0v.x),
                                      o01 - __half2float(h0v.y));
                uint32_t h1 = pack_h2(o10, o11);
                __half2 h1v = *(__half2*)&h1;
                uint32_t l1 = pack_h2(o10 - __half2float(h1v.x),
                                      o11 - __half2float(h1v.y));
                *(uint32_t*)(Ch + (size_t)r0 * G_N + n)       = h0;
                *(uint32_t*)(Cl + (size_t)r0 * G_N + n)       = l0;
                *(uint32_t*)(Ch + (size_t)(r0 + 8) * G_N + n) = h1;
                *(uint32_t*)(Cl + (size_t)(r0 + 8) * G_N + n) = l1;
            } else {
                *(uint32_t*)(Ch + (size_t)r0 * G_N + n)       = pack_h2(o00, o01);
                *(uint32_t*)(Ch + (size_t)(r0 + 8) * G_N + n) = pack_h2(o10, o11);
            }
        }
    }
}

// ---------------- Flash attention (fp16 HMMA + cp.async KV pipeline) ---------
// S = (Qh+Ql) K^T (2-term), O += P V (1-term).
#define FKSM 8192
#define FSTG (2 * FKSM + 256)
#define FSM_STG0 32768
#define FLASH_SMEM (32768 + 2 * FSTG)  // 66048

__device__ __forceinline__ void kv_prefetch(
    uint32_t us, const __half* __restrict__ K_, const __half* __restrict__ V_,
    size_t baseK, int kt, const int* __restrict__ maskp, int tid)
{
#pragma unroll
    for (int it = 0; it < 2; it++) {
        int c = tid + it * 256;
        int r = c >> 3, c16 = c & 7;
        uint32_t sw = (uint32_t)(r * 128 + ((c16 ^ (r & 7)) << 4));
        size_t src = baseK + (size_t)(kt * 64 + r) * DMODEL + c16 * 8;
        cp16(us + sw,        K_ + src);
        cp16(us + FKSM + sw, V_ + src);
    }
    if (tid < 16) cp16(us + 2 * FKSM + tid * 16, maskp + kt * 64 + tid * 4);
}

__global__ __launch_bounds__(256, 1) void flash_hmma(
    const __half* __restrict__ Qh_, const __half* __restrict__ Ql_,
    const __half* __restrict__ K_, const __half* __restrict__ V_,
    const int* __restrict__ mask,
    __half* __restrict__ Oh_, __half* __restrict__ Ol_)
{
    extern __shared__ __align__(1024) char smem[];
    const uint32_t u0 = smem_to_u32(smem);
    char* sQh = smem;
    char* sQl = smem + 16384;

    const int tid = threadIdx.x, lane = tid & 31, wid = tid >> 5;
    const int q0 = blockIdx.x * 128;
    const int h  = blockIdx.y;
    const int b  = blockIdx.z;
    const size_t baseQ = ((size_t)b * SEQ + q0) * DMODEL + h * DK;
    const size_t baseK = ((size_t)b * SEQ) * DMODEL + h * DK;
    const int* maskp = mask + b * SEQ;

    kv_prefetch(u0 + FSM_STG0, K_, V_, baseK, 0, maskp, tid);
    CP_COMMIT();

#pragma unroll
    for (int it = 0; it < 4; it++) {
        int c = tid + it * 256;
        int r = c >> 3, c16 = c & 7;
        uint32_t sw = (uint32_t)(r * 128 + ((c16 ^ (r & 7)) << 4));
        size_t src = baseQ + (size_t)r * DMODEL + c16 * 8;
        *(uint4*)(sQh + sw) = *(const uint4*)(Qh_ + src);
        *(uint4*)(sQl + sw) = *(const uint4*)(Ql_ + src);
    }
    __syncthreads();

    uint32_t fQh[4][4], fQl[4][4];
    {
        const uint32_t uQh = smem_to_u32(sQh), uQl = smem_to_u32(sQl);
        int r = wid * 16 + (lane & 15);
        int colA = lane >> 4;
#pragma unroll
        for (int ks = 0; ks < 4; ks++) {
            uint32_t off = (uint32_t)(r * 128 + (((ks * 2 + colA) ^ (r & 7)) << 4));
            ldm_x4(fQh[ks], uQh + off);
            ldm_x4(fQl[ks], uQl + off);
        }
    }

    float m0 = -1e30f, m1 = -1e30f, l0 = 0.f, l1 = 0.f;
    float oacc[8][4];
#pragma unroll
    for (int d = 0; d < 8; d++)
#pragma unroll
        for (int f = 0; f < 4; f++) oacc[d][f] = 0.f;

    const int rowB = (lane & 7) + ((lane >> 4) << 3);
    const int colB = (lane >> 3) & 1;
    const int rT = lane & 15;
    const int cT = lane >> 4;

    const int NT = SEQ / 64;  // 32
    for (int kt = 0; kt < NT; kt++) {
        const uint32_t us = u0 + FSM_STG0 + (uint32_t)(kt & 1) * FSTG;
        if (kt + 1 < NT) {
            kv_prefetch(u0 + FSM_STG0 + (uint32_t)((kt + 1) & 1) * FSTG,
                        K_, V_, baseK, kt + 1, maskp, tid);
            CP_COMMIT();
            CP_WAIT1();
        } else {
            CP_WAIT0();
        }
        __syncthreads();

        const uint32_t uK = us, uV = us + FKSM;
        const int* smask = (const int*)(smem + FSM_STG0 + (kt & 1) * FSTG + 2 * FKSM);

        float sacc[8][4];
#pragma unroll
        for (int nj = 0; nj < 8; nj++)
#pragma unroll
            for (int f = 0; f < 4; f++) sacc[nj][f] = 0.f;

#pragma unroll
        for (int ks = 0; ks < 4; ks++) {
            uint32_t fK[4][4];
#pragma unroll
            for (int nj2 = 0; nj2 < 4; nj2++) {
                int r = nj2 * 16 + rowB;
                uint32_t off = (uint32_t)(r * 128 + (((ks * 2 + colB) ^ (r & 7)) << 4));
                ldm_x4(fK[nj2], uK + off);
            }
#pragma unroll
            for (int nj = 0; nj < 8; nj++) {
                const uint32_t* bb = &fK[nj >> 1][(nj & 1) * 2];
                mma16816(sacc[nj], fQh[ks], bb);
                mma16816(sacc[nj], fQl[ks], bb);
            }
        }

        const float cs = 0.18033688f;  // 0.125 * log2(e)
        float mx0 = -1e30f, mx1 = -1e30f;
#pragma unroll
        for (int nj = 0; nj < 8; nj++) {
            int col = nj * 8 + 2 * (lane & 3);
            bool ma = smask[col] != 0, mb2 = smask[col + 1] != 0;
            float s0 = ma  ? sacc[nj][0] * cs : -1e30f;
            float s1 = mb2 ? sacc[nj][1] * cs : -1e30f;
            float s2 = ma  ? sacc[nj][2] * cs : -1e30f;
            float s3 = mb2 ? sacc[nj][3] * cs : -1e30f;
            sacc[nj][0] = s0; sacc[nj][1] = s1; sacc[nj][2] = s2; sacc[nj][3] = s3;
            mx0 = fmaxf(mx0, fmaxf(s0, s1));
            mx1 = fmaxf(mx1, fmaxf(s2, s3));
        }
        mx0 = fmaxf(mx0, __shfl_xor_sync(0xffffffffu, mx0, 1));
        mx0 = fmaxf(mx0, __shfl_xor_sync(0xffffffffu, mx0, 2));
        mx1 = fmaxf(mx1, __shfl_xor_sync(0xffffffffu, mx1, 1));
        mx1 = fmaxf(mx1, __shfl_xor_sync(0xffffffffu, mx1, 2));

        float mn0 = fmaxf(m0, mx0), mn1 = fmaxf(m1, mx1);
        float cr0 = exp2_fast(m0 - mn0), cr1 = exp2_fast(m1 - mn1);
        m0 = mn0; m1 = mn1;
        l0 *= cr0; l1 *= cr1;
#pragma unroll
        for (int d = 0; d < 8; d++) {
            oacc[d][0] *= cr0; oacc[d][1] *= cr0;
            oacc[d][2] *= cr1; oacc[d][3] *= cr1;
        }

        uint32_t ph01[8], ph23[8];
        float rs0 = 0.f, rs1 = 0.f;
#pragma unroll
        for (int nj = 0; nj < 8; nj++) {
            float p0 = exp2_fast(sacc[nj][0] - mn0);
            float p1 = exp2_fast(sacc[nj][1] - mn0);
            float p2 = exp2_fast(sacc[nj][2] - mn1);
            float p3 = exp2_fast(sacc[nj][3] - mn1);
            rs0 += p0 + p1; rs1 += p2 + p3;
            ph01[nj] = pack_h2(p0, p1);
            ph23[nj] = pack_h2(p2, p3);
        }
        rs0 += __shfl_xor_sync(0xffffffffu, rs0, 1);
        rs0 += __shfl_xor_sync(0xffffffffu, rs0, 2);
        rs1 += __shfl_xor_sync(0xffffffffu, rs1, 1);
        rs1 += __shfl_xor_sync(0xffffffffu, rs1, 2);
        l0 += rs0; l1 += rs1;

#pragma unroll
        for (int kc = 0; kc < 4; kc++) {
            uint32_t aP[4] = { ph01[2 * kc], ph23[2 * kc], ph01[2 * kc + 1], ph23[2 * kc + 1] };
#pragma unroll
            for (int dn = 0; dn < 4; dn++) {
                int r = kc * 16 + rT;
                int c16 = dn * 2 + cT;
                uint32_t off = (uint32_t)(r * 128 + ((c16 ^ (r & 7)) << 4));
                uint32_t tv[4];
                ldm_x4_t(tv, uV + off);
                mma16816(oacc[2 * dn],     aP, &tv[0]);
                mma16816(oacc[2 * dn + 1], aP, &tv[2]);
            }
        }
        __syncthreads();
    }

    float inv0 = 1.f / l0, inv1 = 1.f / l1;
    size_t row0 = (size_t)b * SEQ + q0 + wid * 16 + (lane >> 2);
#pragma unroll
    for (int d = 0; d < 8; d++) {
        int col = h * DK + d * 8 + 2 * (lane & 3);
        float o0 = oacc[d][0] * inv0, o1 = oacc[d][1] * inv0;
        uint32_t hh = pack_h2(o0, o1);
        __half2 h2 = *(__half2*)&hh;
        uint32_t ll = pack_h2(o0 - __half2float(h2.x), o1 - __half2float(h2.y));
        *(uint32_t*)(Oh_ + row0 * DMODEL + col) = hh;
        *(uint32_t*)(Ol_ + row0 * DMODEL + col) = ll;
        float o2 = oacc[d][2] * inv1, o3 = oacc[d][3] * inv1;
        uint32_t hh2 = pack_h2(o2, o3);
        __half2 h3 = *(__half2*)&hh2;
        uint32_t ll2 = pack_h2(o2 - __half2float(h3.x), o3 - __half2float(h3.y));
        *(uint32_t*)(Oh_ + (row0 + 8) * DMODEL + col) = hh2;
        *(uint32_t*)(Ol_ + (row0 + 8) * DMODEL + col) = ll2;
    }
}

// ---------------- launcher ---------------------------------------------------
extern "C" void kernel_launch(void* const* d_in, const int* in_sizes, int n_in,
                              void* d_out, int out_size)
{
    const float* x    = (const float*)d_in[0];
    const int*   mask = (const int*)  d_in[1];
    const float* Wq = (const float*)d_in[2];
    const float* bq = (const float*)d_in[3];
    const float* Wk = (const float*)d_in[4];
    const float* bk = (const float*)d_in[5];
    const float* Wv = (const float*)d_in[6];
    const float* bv = (const float*)d_in[7];
    const float* Wo = (const float*)d_in[8];
    const float* bo = (const float*)d_in[9];
    float* out = (float*)d_out;

    __half *xh, *xl, *w, *qh, *ql, *k, *v;
    cudaGetSymbolAddress((void**)&xh, g_xh);
    cudaGetSymbolAddress((void**)&xl, g_xl);
    cudaGetSymbolAddress((void**)&w,  g_w);
    cudaGetSymbolAddress((void**)&qh, g_qh);
    cudaGetSymbolAddress((void**)&ql, g_ql);
    cudaGetSymbolAddress((void**)&k,  g_k);
    cudaGetSymbolAddress((void**)&v,  g_v);

    const int SMEM1 = 3 * 2 * GSM;  // 96KB  (1-term, 3 stages)
    const int SMEM2 = 3 * 3 * GSM;  // 144KB (2-term, 3 stages)
    cudaFuncSetAttribute(gemm_hmma<1>,
                         cudaFuncAttributeMaxDynamicSharedMemorySize, SMEM1);
    cudaFuncSetAttribute(gemm_hmma<2>,
                         cudaFuncAttributeMaxDynamicSharedMemorySize, SMEM2);
    cudaFuncSetAttribute(flash_hmma,
                         cudaFuncAttributeMaxDynamicSharedMemorySize, FLASH_SMEM);

    const int WSZ = DMODEL * DMODEL;
    const int n4x = MROWS * DMODEL / 4;
    const int n4w = WSZ / 4;

    convert_kernel<<<n4x / 256, 256>>>(x, xh, n4x);
    convert_w4<<<4 * n4w / 256, 256>>>(Wq, Wk, Wv, Wo, w, n4w);

    dim3 ggrid(G_N / 128, MROWS / 128);   // (8, 64)
    gemm_hmma<1><<<ggrid, 256, SMEM1>>>(xh, nullptr, w + 0 * WSZ, bq, nullptr, qh, ql);
    gemm_hmma<1><<<ggrid, 256, SMEM1>>>(xh, nullptr, w + 1 * WSZ, bk, nullptr, k, nullptr);
    gemm_hmma<1><<<ggrid, 256, SMEM1>>>(xh, nullptr, w + 2 * WSZ, bv, nullptr, v, nullptr);

    dim3 fgrid(SEQ / 128, NHEADS, BATCH); // (16, 16, 4)
    flash_hmma<<<fgrid, 256, FLASH_SMEM>>>(qh, ql, k, v, mask, xh, xl);

    gemm_hmma<2><<<ggrid, 256, SMEM2>>>(xh, xl, w + 3 * WSZ, bo, out, nullptr, nullptr);
}